// round 13
// baseline (speedup 1.0000x reference)
#include <cuda_runtime.h>
#include <cuda_bf16.h>
#include <cstdint>
#include <string.h>
#include <math.h>

typedef __nv_bfloat16 bf16;

#define TA 8192
#define TBB 8192
#define STG (2*TA + 2*TBB)
#define STAGES 3
#define SMEM_SZ (1024 + STAGES*STG)   // 99328 -> 2 CTAs/SM

// ---------------- device-global scratch ----------------
__device__ __align__(128) char g_qh[128*32*TA], g_ql[128*32*TA];
__device__ __align__(128) char g_kh[128*32*TA], g_kl[128*32*TA];
__device__ __align__(128) char g_vbh[4*8*128*TBB], g_vbl[4*8*128*TBB];
__device__ __align__(128) char g_wkh[8*32*TBB], g_wkl[8*32*TBB];
__device__ __align__(128) char g_woh[8*32*TBB], g_wol[8*32*TBB];
__device__ __align__(128) char g_wqh[8*32*TA],  g_wql[8*32*TA];
__device__ __align__(128) char g_wvh[8*32*TA],  g_wvl[8*32*TA];
__device__ __align__(128) char g_pkth[4*8*128*TA], g_pktl[4*8*128*TA];
__device__ __align__(128) char g_wvwoh[8*32*TBB], g_wvwol[8*32*TBB];
__device__ __align__(128) char g_kvrh[4*8*32*TA], g_kvrl[4*8*32*TA];
__device__ __align__(128) char g_kvoh[4*8*32*TBB], g_kvol[4*8*32*TBB];
__device__ __align__(128) char g_finh[4*8*32*TBB], g_finl[4*8*32*TBB];
__device__ unsigned int g_barA[4];
__device__ unsigned int g_barD[4];

// ---------------- PTX helpers ----------------
__device__ __forceinline__ uint32_t s2u(const void* p) {
    uint32_t a;
    asm("{ .reg .u64 t; cvta.to.shared.u64 t, %1; cvt.u32.u64 %0, t; }" : "=r"(a) : "l"(p));
    return a;
}
#define MBARRIER_INIT(addr, cnt) \
    asm volatile("mbarrier.init.shared.b64 [%0], %1;" :: "r"((uint32_t)(addr)), "r"((uint32_t)(cnt)) : "memory")
#define MBARRIER_EXPECT_TX(addr, bytes) \
    asm volatile("mbarrier.arrive.expect_tx.shared.b64 _, [%0], %1;" :: "r"((uint32_t)(addr)), "r"((uint32_t)(bytes)) : "memory")
#define MBARRIER_WAIT_PARITY(mbar, par) do { \
    uint32_t _m = (uint32_t)(mbar); uint32_t _p = (uint32_t)(par); uint32_t _d; \
    asm volatile("{\n\t.reg .pred p;\n\tmbarrier.try_wait.parity.acquire.cta.shared::cta.b64 p, [%1], %2;\n\tselp.b32 %0, 1, 0, p;\n\t}" \
        : "=r"(_d) : "r"(_m), "r"(_p) : "memory"); \
    if (!_d) { \
        asm volatile("{\n\t.reg .pred P1;\n\tWL_%=:\n\tmbarrier.try_wait.parity.acquire.cta.shared::cta.b64 P1, [%0], %1, 0x989680;\n\t@P1 bra.uni WD_%=;\n\tbra.uni WL_%=;\n\tWD_%=:\n\t}" \
            :: "r"(_m), "r"(_p) : "memory"); \
    } \
} while(0)

__device__ __forceinline__ void bulk_g2s(uint32_t dst, const void* src, uint32_t bytes, uint32_t mbar) {
    asm volatile("cp.async.bulk.shared::cluster.global.mbarrier::complete_tx::bytes [%0], [%1], %2, [%3];"
        :: "r"(dst), "l"(src), "r"(bytes), "r"(mbar) : "memory");
}
__device__ __forceinline__ void ldsm4(uint32_t* r, uint32_t a) {
    asm volatile("ldmatrix.sync.aligned.m8n8.x4.shared.b16 {%0,%1,%2,%3}, [%4];"
        : "=r"(r[0]), "=r"(r[1]), "=r"(r[2]), "=r"(r[3]) : "r"(a));
}
__device__ __forceinline__ void ldsm4t(uint32_t* r, uint32_t a) {
    asm volatile("ldmatrix.sync.aligned.m8n8.x4.trans.shared.b16 {%0,%1,%2,%3}, [%4];"
        : "=r"(r[0]), "=r"(r[1]), "=r"(r[2]), "=r"(r[3]) : "r"(a));
}
__device__ __forceinline__ void mma16816(float* c, const uint32_t* a, const uint32_t* b) {
    asm volatile("mma.sync.aligned.m16n8k16.row.col.f32.bf16.bf16.f32 "
        "{%0,%1,%2,%3}, {%4,%5,%6,%7}, {%8,%9}, {%0,%1,%2,%3};"
        : "+f"(c[0]), "+f"(c[1]), "+f"(c[2]), "+f"(c[3])
        : "r"(a[0]), "r"(a[1]), "r"(a[2]), "r"(a[3]), "r"(b[0]), "r"(b[1]));
}

__device__ __forceinline__ unsigned short bfraw(bf16 h) { unsigned short u; memcpy(&u, &h, 2); return u; }
__device__ __forceinline__ void split2(float x, float y, uint32_t& H, uint32_t& L) {
    bf16 hx = __float2bfloat16(x), hy = __float2bfloat16(y);
    bf16 lx = __float2bfloat16(x - __bfloat162float(hx));
    bf16 ly = __float2bfloat16(y - __bfloat162float(hy));
    H = (uint32_t)bfraw(hx) | ((uint32_t)bfraw(hy) << 16);
    L = (uint32_t)bfraw(lx) | ((uint32_t)bfraw(ly) << 16);
}

__device__ __forceinline__ uint32_t a_off(int row, int kbyte) {
    int p = row >> 1;
    int c = (row & 1) * 4 + (kbyte >> 4);
    return (uint32_t)p * 128 + (uint32_t)((c ^ (p & 7)) * 16) + (kbyte & 15);
}
__device__ __forceinline__ uint32_t b_off(int r, int nbyte) {
    int q = nbyte >> 7;
    int c = (nbyte & 127) >> 4;
    return (uint32_t)q * 4096 + (uint32_t)r * 128 + (uint32_t)((c ^ (r & 7)) * 16) + (nbyte & 15);
}

// grid-wide barrier for all-resident launches (n = total blocks)
__device__ __forceinline__ void grid_bar(int idx, unsigned int n) {
    __syncthreads();
    if (threadIdx.x == 0) {
        __threadfence();
        atomicAdd(&g_barA[idx], 1u);
        while (*((volatile unsigned int*)&g_barA[idx]) < n) __nanosleep(64);
        __threadfence();
        unsigned int d = atomicAdd(&g_barD[idx], 1u);
        if (d == n - 1) {
            *((volatile unsigned int*)&g_barA[idx]) = 0;
            __threadfence();
            *((volatile unsigned int*)&g_barD[idx]) = 0;
        }
    }
    __syncthreads();
}

// ---------------- conversions (R11 versions) ----------------
__global__ void conv_acts(const float* __restrict__ q, const float* __restrict__ k,
                          const float* __restrict__ v) {
    int zz = blockIdx.y;
    const float* src = zz == 0 ? q : zz == 1 ? k : v;
    int idx = blockIdx.x * 256 + threadIdx.x;
    int m = idx >> 7;
    int u0 = (idx & 127) << 3;
    const float4* s = reinterpret_cast<const float4*>(src + ((size_t)m << 10) + u0);
    float4 a = s[0], b = s[1];
    uint32_t h[4], l[4];
    split2(a.x, a.y, h[0], l[0]); split2(a.z, a.w, h[1], l[1]);
    split2(b.x, b.y, h[2], l[2]); split2(b.z, b.w, h[3], l[3]);
    if (zz < 2) {
        char* hi = zz == 0 ? g_qh : g_kh;
        char* lo = zz == 0 ? g_ql : g_kl;
        size_t tile = ((size_t)(m >> 7) * 32 + (u0 >> 5)) * TA;
        uint32_t off = a_off(m & 127, (u0 & 31) * 2);
        *reinterpret_cast<uint4*>(hi + tile + off) = make_uint4(h[0], h[1], h[2], h[3]);
        *reinterpret_cast<uint4*>(lo + tile + off) = make_uint4(l[0], l[1], l[2], l[3]);
    } else {
        int batch = m >> 12, sloc = m & 4095;
        size_t tile = ((size_t)(batch * 8 + (u0 >> 7)) * 128 + (sloc >> 5)) * TBB;
        uint32_t off = b_off(sloc & 31, (u0 & 127) * 2);
        *reinterpret_cast<uint4*>(g_vbh + tile + off) = make_uint4(h[0], h[1], h[2], h[3]);
        *reinterpret_cast<uint4*>(g_vbl + tile + off) = make_uint4(l[0], l[1], l[2], l[3]);
    }
}
__global__ void conv_ws(const float* __restrict__ Wk, const float* __restrict__ Wo,
                        const float* __restrict__ Wq, const float* __restrict__ Wv) {
    int zz = blockIdx.y;
    const float* W = zz == 0 ? Wk : zz == 1 ? Wo : zz == 2 ? Wq : Wv;
    int idx = blockIdx.x * 256 + threadIdx.x;
    int r = idx >> 7;
    int c0 = (idx & 127) << 3;
    const float4* s = reinterpret_cast<const float4*>(W + ((size_t)r << 10) + c0);
    float4 a = s[0], b = s[1];
    uint32_t h[4], l[4];
    split2(a.x, a.y, h[0], l[0]); split2(a.z, a.w, h[1], l[1]);
    split2(b.x, b.y, h[2], l[2]); split2(b.z, b.w, h[3], l[3]);
    if (zz < 2) {
        char* hi = zz == 0 ? g_wkh : g_woh;
        char* lo = zz == 0 ? g_wkl : g_wol;
        size_t tile = ((size_t)(c0 >> 7) * 32 + (r >> 5)) * TBB;
        uint32_t off = b_off(r & 31, (c0 & 127) * 2);
        *reinterpret_cast<uint4*>(hi + tile + off) = make_uint4(h[0], h[1], h[2], h[3]);
        *reinterpret_cast<uint4*>(lo + tile + off) = make_uint4(l[0], l[1], l[2], l[3]);
    } else {
        char* hi = zz == 2 ? g_wqh : g_wvh;
        char* lo = zz == 2 ? g_wql : g_wvl;
        size_t tile = ((size_t)(r >> 7) * 32 + (c0 >> 5)) * TA;
        uint32_t off = a_off(r & 127, (c0 & 31) * 2);
        *reinterpret_cast<uint4*>(hi + tile + off) = make_uint4(h[0], h[1], h[2], h[3]);
        *reinterpret_cast<uint4*>(lo + tile + off) = make_uint4(l[0], l[1], l[2], l[3]);
    }
}

// ---------------- shared GEMM mainloop ----------------
__device__ __forceinline__ void refill(uint32_t st0, uint32_t sb, int s,
        const char* Abh, const char* Abl, const char* Bbh, const char* Bbl, int c) {
    MBARRIER_EXPECT_TX(sb + 8 * s, STG);
    uint32_t d = st0 + s * STG;
    bulk_g2s(d,            Abh + (size_t)c * TA,  TA,  sb + 8 * s);
    bulk_g2s(d + TA,       Abl + (size_t)c * TA,  TA,  sb + 8 * s);
    bulk_g2s(d + 2 * TA,   Bbh + (size_t)c * TBB, TBB, sb + 8 * s);
    bulk_g2s(d + 2*TA+TBB, Bbl + (size_t)c * TBB, TBB, sb + 8 * s);
}

__device__ __forceinline__ void gemm_core(
        const char* __restrict__ Abh, const char* __restrict__ Abl,
        const char* __restrict__ Bbh, const char* __restrict__ Bbl,
        int kch, uint32_t sb, uint32_t st0, float acc[4][4][4]) {
    const int tid = threadIdx.x, lane = tid & 31, wid = tid >> 5;
    const int wm = wid >> 2, wn = wid & 3;
    const int i = lane & 15, h = lane >> 4;

    if (tid == 0)
        for (int s = 0; s < STAGES; ++s) MBARRIER_INIT(sb + 8 * s, 1);
    __syncthreads();

    if (tid == 0) {
        int np = STAGES < kch ? STAGES : kch;
        for (int s = 0; s < np; ++s) refill(st0, sb, s, Abh, Abl, Bbh, Bbl, s);
    }

#pragma unroll
    for (int ii = 0; ii < 4; ii++)
#pragma unroll
        for (int j = 0; j < 4; j++)
#pragma unroll
            for (int r = 0; r < 4; r++) acc[ii][j][r] = 0.0f;

    const uint32_t aBase = (uint32_t)wm * 4096 + (uint32_t)(i >> 1) * 128;
    const int xA = (i >> 1) & 7;
    const int cA0 = (i & 1) * 4 + h;
    const uint32_t qOff = (uint32_t)(wn >> 1) * 4096;
    const int xB = lane & 7;
    const uint32_t pj0 = (uint32_t)((((wn & 1) * 4 + h)     ^ xB) * 16);
    const uint32_t pj1 = (uint32_t)((((wn & 1) * 4 + h + 2) ^ xB) * 16);
    const uint32_t bRow = (uint32_t)i * 128;

    int s = 0, pf = 0;
    for (int c = 0; c < kch; ++c) {
        MBARRIER_WAIT_PARITY(sb + 8 * s, pf);
        uint32_t sa = st0 + s * STG;
#pragma unroll
        for (int k16 = 0; k16 < 2; ++k16) {
            uint32_t bb = sa + 2 * TA + qOff + bRow + k16 * 2048;
            uint32_t bh[4][2], bl4[4][2], t[4];
            ldsm4t(t, bb + pj0);        bh[0][0]=t[0]; bh[0][1]=t[1]; bh[1][0]=t[2]; bh[1][1]=t[3];
            ldsm4t(t, bb + pj1);        bh[2][0]=t[0]; bh[2][1]=t[1]; bh[3][0]=t[2]; bh[3][1]=t[3];
            ldsm4t(t, bb + TBB + pj0);  bl4[0][0]=t[0]; bl4[0][1]=t[1]; bl4[1][0]=t[2]; bl4[1][1]=t[3];
            ldsm4t(t, bb + TBB + pj1);  bl4[2][0]=t[0]; bl4[2][1]=t[1]; bl4[3][0]=t[2]; bl4[3][1]=t[3];
            uint32_t aoff = (uint32_t)(((cA0 + k16 * 2) ^ xA) * 16);
            uint32_t ab = sa + aBase + aoff;
#pragma unroll
            for (int mf = 0; mf < 4; ++mf) {
                uint32_t ah[4], al4[4];
                ldsm4(ah, ab + mf * 1024);
                ldsm4(al4, ab + TA + mf * 1024);
#pragma unroll
                for (int nf = 0; nf < 4; ++nf) {
                    mma16816(acc[mf][nf], ah, bh[nf]);
                    mma16816(acc[mf][nf], al4, bh[nf]);
                    mma16816(acc[mf][nf], ah, bl4[nf]);
                }
            }
        }
        __syncthreads();
        if (tid == 0 && c + STAGES < kch)
            refill(st0, sb, s, Abh, Abl, Bbh, Bbl, c + STAGES);
        if (++s == STAGES) { s = 0; pf ^= 1; }
    }
}

// ---------------- epilogue helpers ----------------
__device__ __forceinline__ void epi_alayout(float acc[4][4][4], char* outH, char* outL,
                                            size_t mtile_base) {
    const int lane = threadIdx.x & 31, wid = threadIdx.x >> 5;
    const int wm = wid >> 2, wn = wid & 3;
    const int g = lane >> 2, tg = lane & 3;
    size_t mtile = (mtile_base + wn) * TA;
#pragma unroll
    for (int mf = 0; mf < 4; ++mf)
#pragma unroll
        for (int nf = 0; nf < 4; ++nf)
#pragma unroll
            for (int rh = 0; rh < 2; ++rh) {
                int row = wm * 64 + mf * 16 + g + rh * 8;
                uint32_t hw, lw;
                split2(acc[mf][nf][rh * 2], acc[mf][nf][rh * 2 + 1], hw, lw);
                uint32_t off = a_off(row, nf * 16 + tg * 4);
                *reinterpret_cast<uint32_t*>(outH + mtile + off) = hw;
                *reinterpret_cast<uint32_t*>(outL + mtile + off) = lw;
            }
}
__device__ __forceinline__ void epi_blayout(float acc[4][4][4], char* outH, char* outL,
                                            size_t nkbase, int m0) {
    const int lane = threadIdx.x & 31, wid = threadIdx.x >> 5;
    const int wm = wid >> 2, wn = wid & 3;
    const int g = lane >> 2, tg = lane & 3;
#pragma unroll
    for (int mf = 0; mf < 4; ++mf)
#pragma unroll
        for (int rh = 0; rh < 2; ++rh) {
            int row = wm * 64 + mf * 16 + g + rh * 8;
            int kloc = m0 + row;
            size_t tile = (nkbase + (kloc >> 5)) * TBB;
#pragma unroll
            for (int nf = 0; nf < 4; ++nf) {
                uint32_t hw, lw;
                split2(acc[mf][nf][rh * 2], acc[mf][nf][rh * 2 + 1], hw, lw);
                uint32_t off = b_off(kloc & 31, (wn * 32 + nf * 8 + tg * 2) * 2);
                *reinterpret_cast<uint32_t*>(outH + tile + off) = hw;
                *reinterpret_cast<uint32_t*>(outL + tile + off) = lw;
            }
        }
}

// ---------------- GEMM kernels ----------------
// Merged: blocks 0..1023 pk3T tiles; blocks 1024..1087 WvWo (tail-fill).
__global__ void __launch_bounds__(256, 2)
projkB_gemm(const float* __restrict__ mask) {
    extern __shared__ __align__(1024) char smem[];
    uint32_t sb = s2u(smem), st0 = sb + 1024;
    const int tid = threadIdx.x, lane = tid & 31, wid = tid >> 5;
    const int wm = wid >> 2, wn = wid & 3;
    const int g = lane >> 2, tg = lane & 3;
    const int bid = blockIdx.x;

    if (bid >= 1024) {
        int b2 = bid - 1024;
        int by = b2 >> 3, bx = b2 & 7;
        float acc[4][4][4];
        gemm_core(g_wvh + (size_t)by * 32 * TA, g_wvl + (size_t)by * 32 * TA,
                  g_woh + (size_t)bx * 32 * TBB, g_wol + (size_t)bx * 32 * TBB,
                  32, sb, st0, acc);
        epi_blayout(acc, g_wvwoh, g_wvwol, (size_t)bx * 32, by * 128);
        return;
    }

    const int by = bid >> 3, bx = bid & 7;
    const int m0 = by * 128;

    float acc[4][4][4];
    gemm_core(g_kh + (size_t)by * 32 * TA, g_kl + (size_t)by * 32 * TA,
              g_wkh + (size_t)bx * 32 * TBB, g_wkl + (size_t)bx * 32 * TBB,
              32, sb, st0, acc);
    __syncthreads();

    uint32_t shh = st0, sll = st0 + 34816;
#pragma unroll
    for (int mf = 0; mf < 4; ++mf)
#pragma unroll
        for (int rh = 0; rh < 2; ++rh) {
            int row = wm * 64 + mf * 16 + g + rh * 8;
            float mv = mask[m0 + row];
#pragma unroll
            for (int nf = 0; nf < 4; ++nf) {
                float v0 = acc[mf][nf][rh * 2] * mv;
                float v1 = acc[mf][nf][rh * 2 + 1] * mv;
                v0 = v0 / (1.0f + __expf(-v0)) * mv;
                v1 = v1 / (1.0f + __expf(-v1)) * mv;
                uint32_t hw, lw;
                split2(v0, v1, hw, lw);
                uint32_t a = (uint32_t)row * 272 + (wn * 32 + nf * 8 + tg * 2) * 2;
                asm volatile("st.shared.b32 [%0], %1;" :: "r"(shh + a), "r"(hw) : "memory");
                asm volatile("st.shared.b32 [%0], %1;" :: "r"(sll + a), "r"(lw) : "memory");
            }
        }
    __syncthreads();
    int u = tid & 127;
    int sh2 = (tid >> 7) * 64;
    int bt = by >> 5;
    int kc0 = (m0 & 4095) >> 5;
#pragma unroll
    for (int c8 = 0; c8 < 8; ++c8) {
        int s0 = sh2 + c8 * 8;
        uint32_t hw[4], lw[4];
#pragma unroll
        for (int p = 0; p < 4; ++p) {
            unsigned short h0, h1, l0, l1;
            uint32_t a0 = (uint32_t)(s0 + 2 * p) * 272 + (uint32_t)u * 2;
            uint32_t a1 = a0 + 272;
            asm volatile("ld.shared.b16 %0, [%1];" : "=h"(h0) : "r"(shh + a0));
            asm volatile("ld.shared.b16 %0, [%1];" : "=h"(h1) : "r"(shh + a1));
            asm volatile("ld.shared.b16 %0, [%1];" : "=h"(l0) : "r"(sll + a0));
            asm volatile("ld.shared.b16 %0, [%1];" : "=h"(l1) : "r"(sll + a1));
            hw[p] = (uint32_t)h0 | ((uint32_t)h1 << 16);
            lw[p] = (uint32_t)l0 | ((uint32_t)l1 << 16);
        }
        size_t tile = ((size_t)(bt * 8 + bx) * 128 + kc0 + (s0 >> 5)) * TA;
        uint32_t off = a_off(u, (s0 & 31) * 2);
        *reinterpret_cast<uint4*>(g_pkth + tile + off) = make_uint4(hw[0], hw[1], hw[2], hw[3]);
        *reinterpret_cast<uint4*>(g_pktl + tile + off) = make_uint4(lw[0], lw[1], lw[2], lw[3]);
    }
}

// Fused kvr -> kvo -> wqkvo -> final (4 tiles/block), 256 blocks all resident.
__global__ void __launch_bounds__(256, 2)
kvx_gemm(float* __restrict__ outF) {
    extern __shared__ __align__(1024) char smem[];
    uint32_t sb = s2u(smem), st0 = sb + 1024;
    const int tid = threadIdx.x, lane = tid & 31, wid = tid >> 5;
    const int wm = wid >> 2, wn = wid & 3;
    const int g = lane >> 2, tg = lane & 3;
    const int bid = blockIdx.x;
    const int b = bid >> 6, by = (bid >> 3) & 7, bx = bid & 7;

    float acc[4][4][4];
    // Phase 1: kvr[b] = pk3T[b] @ v[b]  (K=4096)
    gemm_core(g_pkth + (size_t)(b * 8 + by) * 128 * TA, g_pktl + (size_t)(b * 8 + by) * 128 * TA,
              g_vbh + (size_t)(b * 8 + bx) * 128 * TBB, g_vbl + (size_t)(b * 8 + bx) * 128 * TBB,
              128, sb, st0, acc);
    epi_alayout(acc, g_kvrh, g_kvrl, (size_t)(b * 8 + by) * 32 + bx * 4);

    grid_bar(0, 256);

    // Phase 2: kvo[b] = kvr[b] @ WvWo
    gemm_core(g_kvrh + (size_t)(b * 8 + by) * 32 * TA, g_kvrl + (size_t)(b * 8 + by) * 32 * TA,
              g_wvwoh + (size_t)bx * 32 * TBB, g_wvwol + (size_t)bx * 32 * TBB,
              32, sb, st0, acc);
    epi_blayout(acc, g_kvoh, g_kvol, (size_t)(b * 8 + bx) * 32, by * 128);

    grid_bar(1, 256);

    // Phase 3: fin[b] = Wq @ kvo[b]
    gemm_core(g_wqh + (size_t)by * 32 * TA, g_wql + (size_t)by * 32 * TA,
              g_kvoh + (size_t)(b * 8 + bx) * 32 * TBB, g_kvol + (size_t)(b * 8 + bx) * 32 * TBB,
              32, sb, st0, acc);
    epi_blayout(acc, g_finh, g_finl, (size_t)(b * 8 + bx) * 32, by * 128);

    grid_bar(2, 256);

    // Phase 4: out = q @ fin, 1024 tiles / 256 blocks = 4 tiles each (perfect balance)
#pragma unroll 1
    for (int t = 0; t < 4; ++t) {
        int tileid = bid * 4 + t;
        int mb = tileid >> 3;          // 0..127 (global M tile; batch = mb>>5)
        int bx2 = tileid & 7;
        int z = mb >> 5;
        gemm_core(g_qh + (size_t)mb * 32 * TA, g_ql + (size_t)mb * 32 * TA,
                  g_finh + (size_t)(z * 8 + bx2) * 32 * TBB, g_finl + (size_t)(z * 8 + bx2) * 32 * TBB,
                  32, sb, st0, acc);
        int n0 = bx2 * 128;
#pragma unroll
        for (int mf = 0; mf < 4; ++mf)
#pragma unroll
            for (int nf = 0; nf < 4; ++nf)
#pragma unroll
                for (int rh = 0; rh < 2; ++rh) {
                    int row = wm * 64 + mf * 16 + g + rh * 8;
                    int gcol = n0 + wn * 32 + nf * 8 + tg * 2;
                    float2 v = make_float2(acc[mf][nf][rh * 2], acc[mf][nf][rh * 2 + 1]);
                    *reinterpret_cast<float2*>(outF + ((size_t)mb * 128 + row) * 1024 + gcol) = v;
                }
        __syncthreads();   // smem stage reuse across tiles
    }
}

// ---------------- launch ----------------
extern "C" void kernel_launch(void* const* d_in, const int* in_sizes, int n_in,
                              void* d_out, int out_size) {
    const float* query = (const float*)d_in[0];
    const float* key   = (const float*)d_in[1];
    const float* value = (const float*)d_in[2];
    const float* mask  = (const float*)d_in[3];
    const float* Wk    = (const float*)d_in[4];
    const float* Wv    = (const float*)d_in[5];
    const float* Wq    = (const float*)d_in[6];
    const float* Wo    = (const float*)d_in[7];
    float* out = (float*)d_out;

    static bool attr_done = false;
    if (!attr_done) {
        cudaFuncSetAttribute(projkB_gemm, cudaFuncAttributeMaxDynamicSharedMemorySize, SMEM_SZ);
        cudaFuncSetAttribute(kvx_gemm,    cudaFuncAttributeMaxDynamicSharedMemorySize, SMEM_SZ);
        attr_done = true;
    }

    conv_acts<<<dim3(8192, 3), 256>>>(query, key, value);
    conv_ws<<<dim3(512, 4), 256>>>(Wk, Wo, Wq, Wv);

    projkB_gemm<<<1088, 256, SMEM_SZ>>>(mask);
    kvx_gemm<<<256, 256, SMEM_SZ>>>(out);
}

// round 14
// speedup vs baseline: 1.0615x; 1.0615x over previous
#include <cuda_runtime.h>
#include <cuda_bf16.h>
#include <cstdint>
#include <string.h>
#include <math.h>

typedef __nv_bfloat16 bf16;

#define TA 8192
#define TBB 8192
#define STG (2*TA + 2*TBB)
#define STAGES 3
#define SMEM_SZ (1024 + STAGES*STG)   // 99328 -> 2 CTAs/SM

// ---------------- device-global scratch ----------------
__device__ __align__(128) char g_qh[128*32*TA], g_ql[128*32*TA];
__device__ __align__(128) char g_kh[128*32*TA], g_kl[128*32*TA];
__device__ __align__(128) char g_vbh[4*8*128*TBB], g_vbl[4*8*128*TBB];
__device__ __align__(128) char g_wkh[8*32*TBB], g_wkl[8*32*TBB];
__device__ __align__(128) char g_woh[8*32*TBB], g_wol[8*32*TBB];
__device__ __align__(128) char g_wqh[8*32*TA],  g_wql[8*32*TA];
__device__ __align__(128) char g_wvh[8*32*TA],  g_wvl[8*32*TA];
__device__ __align__(128) char g_pkth[4*8*128*TA], g_pktl[4*8*128*TA];
__device__ __align__(128) char g_wvwoh[8*32*TBB], g_wvwol[8*32*TBB];
__device__ __align__(128) char g_kvrh[4*8*32*TA], g_kvrl[4*8*32*TA];
__device__ __align__(128) char g_kvoh[4*8*32*TBB], g_kvol[4*8*32*TBB];
__device__ __align__(128) char g_finh[4*8*32*TBB], g_finl[4*8*32*TBB];
__device__ unsigned int g_barA[2];
__device__ unsigned int g_barD[2];

// ---------------- PTX helpers ----------------
__device__ __forceinline__ uint32_t s2u(const void* p) {
    uint32_t a;
    asm("{ .reg .u64 t; cvta.to.shared.u64 t, %1; cvt.u32.u64 %0, t; }" : "=r"(a) : "l"(p));
    return a;
}
#define MBARRIER_INIT(addr, cnt) \
    asm volatile("mbarrier.init.shared.b64 [%0], %1;" :: "r"((uint32_t)(addr)), "r"((uint32_t)(cnt)) : "memory")
#define MBARRIER_EXPECT_TX(addr, bytes) \
    asm volatile("mbarrier.arrive.expect_tx.shared.b64 _, [%0], %1;" :: "r"((uint32_t)(addr)), "r"((uint32_t)(bytes)) : "memory")
#define MBARRIER_WAIT_PARITY(mbar, par) do { \
    uint32_t _m = (uint32_t)(mbar); uint32_t _p = (uint32_t)(par); uint32_t _d; \
    asm volatile("{\n\t.reg .pred p;\n\tmbarrier.try_wait.parity.acquire.cta.shared::cta.b64 p, [%1], %2;\n\tselp.b32 %0, 1, 0, p;\n\t}" \
        : "=r"(_d) : "r"(_m), "r"(_p) : "memory"); \
    if (!_d) { \
        asm volatile("{\n\t.reg .pred P1;\n\tWL_%=:\n\tmbarrier.try_wait.parity.acquire.cta.shared::cta.b64 P1, [%0], %1, 0x989680;\n\t@P1 bra.uni WD_%=;\n\tbra.uni WL_%=;\n\tWD_%=:\n\t}" \
            :: "r"(_m), "r"(_p) : "memory"); \
    } \
} while(0)

__device__ __forceinline__ void bulk_g2s(uint32_t dst, const void* src, uint32_t bytes, uint32_t mbar) {
    asm volatile("cp.async.bulk.shared::cluster.global.mbarrier::complete_tx::bytes [%0], [%1], %2, [%3];"
        :: "r"(dst), "l"(src), "r"(bytes), "r"(mbar) : "memory");
}
__device__ __forceinline__ void ldsm4(uint32_t* r, uint32_t a) {
    asm volatile("ldmatrix.sync.aligned.m8n8.x4.shared.b16 {%0,%1,%2,%3}, [%4];"
        : "=r"(r[0]), "=r"(r[1]), "=r"(r[2]), "=r"(r[3]) : "r"(a));
}
__device__ __forceinline__ void ldsm4t(uint32_t* r, uint32_t a) {
    asm volatile("ldmatrix.sync.aligned.m8n8.x4.trans.shared.b16 {%0,%1,%2,%3}, [%4];"
        : "=r"(r[0]), "=r"(r[1]), "=r"(r[2]), "=r"(r[3]) : "r"(a));
}
__device__ __forceinline__ void mma16816(float* c, const uint32_t* a, const uint32_t* b) {
    asm volatile("mma.sync.aligned.m16n8k16.row.col.f32.bf16.bf16.f32 "
        "{%0,%1,%2,%3}, {%4,%5,%6,%7}, {%8,%9}, {%0,%1,%2,%3};"
        : "+f"(c[0]), "+f"(c[1]), "+f"(c[2]), "+f"(c[3])
        : "r"(a[0]), "r"(a[1]), "r"(a[2]), "r"(a[3]), "r"(b[0]), "r"(b[1]));
}

__device__ __forceinline__ unsigned short bfraw(bf16 h) { unsigned short u; memcpy(&u, &h, 2); return u; }
__device__ __forceinline__ void split2(float x, float y, uint32_t& H, uint32_t& L) {
    bf16 hx = __float2bfloat16(x), hy = __float2bfloat16(y);
    bf16 lx = __float2bfloat16(x - __bfloat162float(hx));
    bf16 ly = __float2bfloat16(y - __bfloat162float(hy));
    H = (uint32_t)bfraw(hx) | ((uint32_t)bfraw(hy) << 16);
    L = (uint32_t)bfraw(lx) | ((uint32_t)bfraw(ly) << 16);
}

__device__ __forceinline__ uint32_t a_off(int row, int kbyte) {
    int p = row >> 1;
    int c = (row & 1) * 4 + (kbyte >> 4);
    return (uint32_t)p * 128 + (uint32_t)((c ^ (p & 7)) * 16) + (kbyte & 15);
}
__device__ __forceinline__ uint32_t b_off(int r, int nbyte) {
    int q = nbyte >> 7;
    int c = (nbyte & 127) >> 4;
    return (uint32_t)q * 4096 + (uint32_t)r * 128 + (uint32_t)((c ^ (r & 7)) * 16) + (nbyte & 15);
}

// grid-wide barrier (n = total participating blocks)
__device__ __forceinline__ void grid_bar(int idx, unsigned int n) {
    __syncthreads();
    if (threadIdx.x == 0) {
        __threadfence();
        atomicAdd(&g_barA[idx], 1u);
        while (*((volatile unsigned int*)&g_barA[idx]) < n) __nanosleep(64);
        __threadfence();
        unsigned int d = atomicAdd(&g_barD[idx], 1u);
        if (d == n - 1) {
            *((volatile unsigned int*)&g_barA[idx]) = 0;
            __threadfence();
            *((volatile unsigned int*)&g_barD[idx]) = 0;
        }
    }
    __syncthreads();
}

// ---------------- conversion bodies ----------------
// one "conv unit" = 256 threads' worth of a [row-chunk] of a 16384x1024 fp32 act
__device__ __forceinline__ void conv_unitA(const float* __restrict__ src, char* hi, char* lo, int idx) {
    int m = idx >> 7;
    int u0 = (idx & 127) << 3;
    const float4* s = reinterpret_cast<const float4*>(src + ((size_t)m << 10) + u0);
    float4 a = s[0], b = s[1];
    uint32_t h[4], l[4];
    split2(a.x, a.y, h[0], l[0]); split2(a.z, a.w, h[1], l[1]);
    split2(b.x, b.y, h[2], l[2]); split2(b.z, b.w, h[3], l[3]);
    size_t tile = ((size_t)(m >> 7) * 32 + (u0 >> 5)) * TA;
    uint32_t off = a_off(m & 127, (u0 & 31) * 2);
    *reinterpret_cast<uint4*>(hi + tile + off) = make_uint4(h[0], h[1], h[2], h[3]);
    *reinterpret_cast<uint4*>(lo + tile + off) = make_uint4(l[0], l[1], l[2], l[3]);
}
__device__ __forceinline__ void conv_unitV(const float* __restrict__ v, int idx) {
    int m = idx >> 7;
    int u0 = (idx & 127) << 3;
    const float4* s = reinterpret_cast<const float4*>(v + ((size_t)m << 10) + u0);
    float4 a = s[0], b = s[1];
    uint32_t h[4], l[4];
    split2(a.x, a.y, h[0], l[0]); split2(a.z, a.w, h[1], l[1]);
    split2(b.x, b.y, h[2], l[2]); split2(b.z, b.w, h[3], l[3]);
    int batch = m >> 12, sloc = m & 4095;
    size_t tile = ((size_t)(batch * 8 + (u0 >> 7)) * 128 + (sloc >> 5)) * TBB;
    uint32_t off = b_off(sloc & 31, (u0 & 127) * 2);
    *reinterpret_cast<uint4*>(g_vbh + tile + off) = make_uint4(h[0], h[1], h[2], h[3]);
    *reinterpret_cast<uint4*>(g_vbl + tile + off) = make_uint4(l[0], l[1], l[2], l[3]);
}

// Launch 1: k conv (blocks 0..8191) + 4 W convs (blocks 8192..10239)
__global__ void conv_kw(const float* __restrict__ key, const float* __restrict__ Wk,
                        const float* __restrict__ Wo, const float* __restrict__ Wq,
                        const float* __restrict__ Wv) {
    int bid = blockIdx.x;
    if (bid < 8192) {
        conv_unitA(key, g_kh, g_kl, bid * 256 + threadIdx.x);
        return;
    }
    int wb = bid - 8192;
    int zz = wb >> 9;             // 0..3
    int xb = wb & 511;
    const float* W = zz == 0 ? Wk : zz == 1 ? Wo : zz == 2 ? Wq : Wv;
    int idx = xb * 256 + threadIdx.x;
    int r = idx >> 7;
    int c0 = (idx & 127) << 3;
    const float4* s = reinterpret_cast<const float4*>(W + ((size_t)r << 10) + c0);
    float4 a = s[0], b = s[1];
    uint32_t h[4], l[4];
    split2(a.x, a.y, h[0], l[0]); split2(a.z, a.w, h[1], l[1]);
    split2(b.x, b.y, h[2], l[2]); split2(b.z, b.w, h[3], l[3]);
    if (zz < 2) {
        char* hi = zz == 0 ? g_wkh : g_woh;
        char* lo = zz == 0 ? g_wkl : g_wol;
        size_t tile = ((size_t)(c0 >> 7) * 32 + (r >> 5)) * TBB;
        uint32_t off = b_off(r & 31, (c0 & 127) * 2);
        *reinterpret_cast<uint4*>(hi + tile + off) = make_uint4(h[0], h[1], h[2], h[3]);
        *reinterpret_cast<uint4*>(lo + tile + off) = make_uint4(l[0], l[1], l[2], l[3]);
    } else {
        char* hi = zz == 2 ? g_wqh : g_wvh;
        char* lo = zz == 2 ? g_wql : g_wvl;
        size_t tile = ((size_t)(r >> 7) * 32 + (c0 >> 5)) * TA;
        uint32_t off = a_off(r & 127, (c0 & 31) * 2);
        *reinterpret_cast<uint4*>(hi + tile + off) = make_uint4(h[0], h[1], h[2], h[3]);
        *reinterpret_cast<uint4*>(lo + tile + off) = make_uint4(l[0], l[1], l[2], l[3]);
    }
}

// ---------------- shared GEMM mainloop ----------------
__device__ __forceinline__ void refill(uint32_t st0, uint32_t sb, int s,
        const char* Abh, const char* Abl, const char* Bbh, const char* Bbl, int c) {
    MBARRIER_EXPECT_TX(sb + 8 * s, STG);
    uint32_t d = st0 + s * STG;
    bulk_g2s(d,            Abh + (size_t)c * TA,  TA,  sb + 8 * s);
    bulk_g2s(d + TA,       Abl + (size_t)c * TA,  TA,  sb + 8 * s);
    bulk_g2s(d + 2 * TA,   Bbh + (size_t)c * TBB, TBB, sb + 8 * s);
    bulk_g2s(d + 2*TA+TBB, Bbl + (size_t)c * TBB, TBB, sb + 8 * s);
}

__device__ __forceinline__ void gemm_core(
        const char* __restrict__ Abh, const char* __restrict__ Abl,
        const char* __restrict__ Bbh, const char* __restrict__ Bbl,
        int kch, uint32_t sb, uint32_t st0, float acc[4][4][4]) {
    const int tid = threadIdx.x, lane = tid & 31, wid = tid >> 5;
    const int wm = wid >> 2, wn = wid & 3;
    const int i = lane & 15, h = lane >> 4;

    if (tid == 0)
        for (int s = 0; s < STAGES; ++s) MBARRIER_INIT(sb + 8 * s, 1);
    __syncthreads();

    if (tid == 0) {
        int np = STAGES < kch ? STAGES : kch;
        for (int s = 0; s < np; ++s) refill(st0, sb, s, Abh, Abl, Bbh, Bbl, s);
    }

#pragma unroll
    for (int ii = 0; ii < 4; ii++)
#pragma unroll
        for (int j = 0; j < 4; j++)
#pragma unroll
            for (int r = 0; r < 4; r++) acc[ii][j][r] = 0.0f;

    const uint32_t aBase = (uint32_t)wm * 4096 + (uint32_t)(i >> 1) * 128;
    const int xA = (i >> 1) & 7;
    const int cA0 = (i & 1) * 4 + h;
    const uint32_t qOff = (uint32_t)(wn >> 1) * 4096;
    const int xB = lane & 7;
    const uint32_t pj0 = (uint32_t)((((wn & 1) * 4 + h)     ^ xB) * 16);
    const uint32_t pj1 = (uint32_t)((((wn & 1) * 4 + h + 2) ^ xB) * 16);
    const uint32_t bRow = (uint32_t)i * 128;

    int s = 0, pf = 0;
    for (int c = 0; c < kch; ++c) {
        MBARRIER_WAIT_PARITY(sb + 8 * s, pf);
        uint32_t sa = st0 + s * STG;
#pragma unroll
        for (int k16 = 0; k16 < 2; ++k16) {
            uint32_t bb = sa + 2 * TA + qOff + bRow + k16 * 2048;
            uint32_t bh[4][2], bl4[4][2], t[4];
            ldsm4t(t, bb + pj0);        bh[0][0]=t[0]; bh[0][1]=t[1]; bh[1][0]=t[2]; bh[1][1]=t[3];
            ldsm4t(t, bb + pj1);        bh[2][0]=t[0]; bh[2][1]=t[1]; bh[3][0]=t[2]; bh[3][1]=t[3];
            ldsm4t(t, bb + TBB + pj0);  bl4[0][0]=t[0]; bl4[0][1]=t[1]; bl4[1][0]=t[2]; bl4[1][1]=t[3];
            ldsm4t(t, bb + TBB + pj1);  bl4[2][0]=t[0]; bl4[2][1]=t[1]; bl4[3][0]=t[2]; bl4[3][1]=t[3];
            uint32_t aoff = (uint32_t)(((cA0 + k16 * 2) ^ xA) * 16);
            uint32_t ab = sa + aBase + aoff;
#pragma unroll
            for (int mf = 0; mf < 4; ++mf) {
                uint32_t ah[4], al4[4];
                ldsm4(ah, ab + mf * 1024);
                ldsm4(al4, ab + TA + mf * 1024);
#pragma unroll
                for (int nf = 0; nf < 4; ++nf) {
                    mma16816(acc[mf][nf], ah, bh[nf]);
                    mma16816(acc[mf][nf], al4, bh[nf]);
                    mma16816(acc[mf][nf], ah, bl4[nf]);
                }
            }
        }
        __syncthreads();
        if (tid == 0 && c + STAGES < kch)
            refill(st0, sb, s, Abh, Abl, Bbh, Bbl, c + STAGES);
        if (++s == STAGES) { s = 0; pf ^= 1; }
    }
}

// ---------------- epilogue helpers ----------------
__device__ __forceinline__ void epi_alayout(float acc[4][4][4], char* outH, char* outL,
                                            size_t mtile_base) {
    const int lane = threadIdx.x & 31, wid = threadIdx.x >> 5;
    const int wm = wid >> 2, wn = wid & 3;
    const int g = lane >> 2, tg = lane & 3;
    size_t mtile = (mtile_base + wn) * TA;
#pragma unroll
    for (int mf = 0; mf < 4; ++mf)
#pragma unroll
        for (int nf = 0; nf < 4; ++nf)
#pragma unroll
            for (int rh = 0; rh < 2; ++rh) {
                int row = wm * 64 + mf * 16 + g + rh * 8;
                uint32_t hw, lw;
                split2(acc[mf][nf][rh * 2], acc[mf][nf][rh * 2 + 1], hw, lw);
                uint32_t off = a_off(row, nf * 16 + tg * 4);
                *reinterpret_cast<uint32_t*>(outH + mtile + off) = hw;
                *reinterpret_cast<uint32_t*>(outL + mtile + off) = lw;
            }
}
__device__ __forceinline__ void epi_blayout(float acc[4][4][4], char* outH, char* outL,
                                            size_t nkbase, int m0) {
    const int lane = threadIdx.x & 31, wid = threadIdx.x >> 5;
    const int wm = wid >> 2, wn = wid & 3;
    const int g = lane >> 2, tg = lane & 3;
#pragma unroll
    for (int mf = 0; mf < 4; ++mf)
#pragma unroll
        for (int rh = 0; rh < 2; ++rh) {
            int row = wm * 64 + mf * 16 + g + rh * 8;
            int kloc = m0 + row;
            size_t tile = (nkbase + (kloc >> 5)) * TBB;
#pragma unroll
            for (int nf = 0; nf < 4; ++nf) {
                uint32_t hw, lw;
                split2(acc[mf][nf][rh * 2], acc[mf][nf][rh * 2 + 1], hw, lw);
                uint32_t off = b_off(kloc & 31, (wn * 32 + nf * 8 + tg * 2) * 2);
                *reinterpret_cast<uint32_t*>(outH + tile + off) = hw;
                *reinterpret_cast<uint32_t*>(outL + tile + off) = lw;
            }
        }
}

// ---------------- GEMM kernels ----------------
// blocks 0..1023: pk3T tiles; 1024..1087: WvWo; 1088..1599: conv(q); 1600..2111: conv(v)
__global__ void __launch_bounds__(256, 2)
projkB_gemm(const float* __restrict__ mask, const float* __restrict__ query,
            const float* __restrict__ value) {
    extern __shared__ __align__(1024) char smem[];
    uint32_t sb = s2u(smem), st0 = sb + 1024;
    const int tid = threadIdx.x, lane = tid & 31, wid = tid >> 5;
    const int wm = wid >> 2, wn = wid & 3;
    const int g = lane >> 2, tg = lane & 3;
    const int bid = blockIdx.x;

    if (bid >= 1088) {
        int cb = bid - 1088;
        if (cb < 512) {
#pragma unroll 1
            for (int it = 0; it < 16; ++it)
                conv_unitA(query, g_qh, g_ql, (cb * 16 + it) * 256 + tid);
        } else {
            cb -= 512;
#pragma unroll 1
            for (int it = 0; it < 16; ++it)
                conv_unitV(value, (cb * 16 + it) * 256 + tid);
        }
        return;
    }
    if (bid >= 1024) {
        int b2 = bid - 1024;
        int by = b2 >> 3, bx = b2 & 7;
        float acc[4][4][4];
        gemm_core(g_wvh + (size_t)by * 32 * TA, g_wvl + (size_t)by * 32 * TA,
                  g_woh + (size_t)bx * 32 * TBB, g_wol + (size_t)bx * 32 * TBB,
                  32, sb, st0, acc);
        epi_blayout(acc, g_wvwoh, g_wvwol, (size_t)bx * 32, by * 128);
        return;
    }

    const int by = bid >> 3, bx = bid & 7;
    const int m0 = by * 128;

    float acc[4][4][4];
    gemm_core(g_kh + (size_t)by * 32 * TA, g_kl + (size_t)by * 32 * TA,
              g_wkh + (size_t)bx * 32 * TBB, g_wkl + (size_t)bx * 32 * TBB,
              32, sb, st0, acc);
    __syncthreads();

    uint32_t shh = st0, sll = st0 + 34816;
#pragma unroll
    for (int mf = 0; mf < 4; ++mf)
#pragma unroll
        for (int rh = 0; rh < 2; ++rh) {
            int row = wm * 64 + mf * 16 + g + rh * 8;
            float mv = mask[m0 + row];
#pragma unroll
            for (int nf = 0; nf < 4; ++nf) {
                float v0 = acc[mf][nf][rh * 2] * mv;
                float v1 = acc[mf][nf][rh * 2 + 1] * mv;
                v0 = v0 / (1.0f + __expf(-v0)) * mv;
                v1 = v1 / (1.0f + __expf(-v1)) * mv;
                uint32_t hw, lw;
                split2(v0, v1, hw, lw);
                uint32_t a = (uint32_t)row * 272 + (wn * 32 + nf * 8 + tg * 2) * 2;
                asm volatile("st.shared.b32 [%0], %1;" :: "r"(shh + a), "r"(hw) : "memory");
                asm volatile("st.shared.b32 [%0], %1;" :: "r"(sll + a), "r"(lw) : "memory");
            }
        }
    __syncthreads();
    int u = tid & 127;
    int sh2 = (tid >> 7) * 64;
    int bt = by >> 5;
    int kc0 = (m0 & 4095) >> 5;
#pragma unroll
    for (int c8 = 0; c8 < 8; ++c8) {
        int s0 = sh2 + c8 * 8;
        uint32_t hw[4], lw[4];
#pragma unroll
        for (int p = 0; p < 4; ++p) {
            unsigned short h0, h1, l0, l1;
            uint32_t a0 = (uint32_t)(s0 + 2 * p) * 272 + (uint32_t)u * 2;
            uint32_t a1 = a0 + 272;
            asm volatile("ld.shared.b16 %0, [%1];" : "=h"(h0) : "r"(shh + a0));
            asm volatile("ld.shared.b16 %0, [%1];" : "=h"(h1) : "r"(shh + a1));
            asm volatile("ld.shared.b16 %0, [%1];" : "=h"(l0) : "r"(sll + a0));
            asm volatile("ld.shared.b16 %0, [%1];" : "=h"(l1) : "r"(sll + a1));
            hw[p] = (uint32_t)h0 | ((uint32_t)h1 << 16);
            lw[p] = (uint32_t)l0 | ((uint32_t)l1 << 16);
        }
        size_t tile = ((size_t)(bt * 8 + bx) * 128 + kc0 + (s0 >> 5)) * TA;
        uint32_t off = a_off(u, (s0 & 31) * 2);
        *reinterpret_cast<uint4*>(g_pkth + tile + off) = make_uint4(hw[0], hw[1], hw[2], hw[3]);
        *reinterpret_cast<uint4*>(g_pktl + tile + off) = make_uint4(lw[0], lw[1], lw[2], lw[3]);
    }
}

// Fused kvr -> kvo -> wqkvo, 256 blocks all resident (R11 version).
__global__ void __launch_bounds__(256, 2)
kvx_gemm() {
    extern __shared__ __align__(1024) char smem[];
    uint32_t sb = s2u(smem), st0 = sb + 1024;
    const int bid = blockIdx.x;
    const int b = bid >> 6, by = (bid >> 3) & 7, bx = bid & 7;

    float acc[4][4][4];
    gemm_core(g_pkth + (size_t)(b * 8 + by) * 128 * TA, g_pktl + (size_t)(b * 8 + by) * 128 * TA,
              g_vbh + (size_t)(b * 8 + bx) * 128 * TBB, g_vbl + (size_t)(b * 8 + bx) * 128 * TBB,
              128, sb, st0, acc);
    epi_alayout(acc, g_kvrh, g_kvrl, (size_t)(b * 8 + by) * 32 + bx * 4);

    grid_bar(0, 256);

    gemm_core(g_kvrh + (size_t)(b * 8 + by) * 32 * TA, g_kvrl + (size_t)(b * 8 + by) * 32 * TA,
              g_wvwoh + (size_t)bx * 32 * TBB, g_wvwol + (size_t)bx * 32 * TBB,
              32, sb, st0, acc);
    epi_blayout(acc, g_kvoh, g_kvol, (size_t)(b * 8 + bx) * 32, by * 128);

    grid_bar(1, 256);

    gemm_core(g_wqh + (size_t)by * 32 * TA, g_wql + (size_t)by * 32 * TA,
              g_kvoh + (size_t)(b * 8 + bx) * 32 * TBB, g_kvol + (size_t)(b * 8 + bx) * 32 * TBB,
              32, sb, st0, acc);
    epi_blayout(acc, g_finh, g_finl, (size_t)(b * 8 + bx) * 32, by * 128);
}

// out[b] = q[b] @ fin[b] -> f32 (R11 version)
__global__ void __launch_bounds__(256, 2)
final_gemm(float* __restrict__ outF) {
    extern __shared__ __align__(1024) char smem[];
    uint32_t sb = s2u(smem), st0 = sb + 1024;
    const int tid = threadIdx.x, lane = tid & 31, wid = tid >> 5;
    const int wm = wid >> 2, wn = wid & 3;
    const int bx = blockIdx.x, by = blockIdx.y, z = blockIdx.z;
    const int g = lane >> 2, tg = lane & 3;
    const int mb = z * 32 + by;
    const int n0 = bx * 128;

    float acc[4][4][4];
    gemm_core(g_qh + (size_t)mb * 32 * TA, g_ql + (size_t)mb * 32 * TA,
              g_finh + (size_t)(z * 8 + bx) * 32 * TBB, g_finl + (size_t)(z * 8 + bx) * 32 * TBB,
              32, sb, st0, acc);

#pragma unroll
    for (int mf = 0; mf < 4; ++mf)
#pragma unroll
        for (int nf = 0; nf < 4; ++nf)
#pragma unroll
            for (int rh = 0; rh < 2; ++rh) {
                int row = wm * 64 + mf * 16 + g + rh * 8;
                int gcol = n0 + wn * 32 + nf * 8 + tg * 2;
                float2 v = make_float2(acc[mf][nf][rh * 2], acc[mf][nf][rh * 2 + 1]);
                *reinterpret_cast<float2*>(outF + ((size_t)mb * 128 + row) * 1024 + gcol) = v;
            }
}

// ---------------- launch ----------------
extern "C" void kernel_launch(void* const* d_in, const int* in_sizes, int n_in,
                              void* d_out, int out_size) {
    const float* query = (const float*)d_in[0];
    const float* key   = (const float*)d_in[1];
    const float* value = (const float*)d_in[2];
    const float* mask  = (const float*)d_in[3];
    const float* Wk    = (const float*)d_in[4];
    const float* Wv    = (const float*)d_in[5];
    const float* Wq    = (const float*)d_in[6];
    const float* Wo    = (const float*)d_in[7];
    float* out = (float*)d_out;

    static bool attr_done = false;
    if (!attr_done) {
        cudaFuncSetAttribute(projkB_gemm, cudaFuncAttributeMaxDynamicSharedMemorySize, SMEM_SZ);
        cudaFuncSetAttribute(kvx_gemm,    cudaFuncAttributeMaxDynamicSharedMemorySize, SMEM_SZ);
        cudaFuncSetAttribute(final_gemm,  cudaFuncAttributeMaxDynamicSharedMemorySize, SMEM_SZ);
        attr_done = true;
    }

    conv_kw<<<10240, 256>>>(key, Wk, Wo, Wq, Wv);
    projkB_gemm<<<2112, 256, SMEM_SZ>>>(mask, query, value);
    kvx_gemm<<<256, 256, SMEM_SZ>>>();
    final_gemm<<<dim3(8, 32, 4), 256, SMEM_SZ>>>(out);
}

// round 15
// speedup vs baseline: 1.1587x; 1.0915x over previous
#include <cuda_runtime.h>
#include <cuda_bf16.h>
#include <cuda_fp16.h>
#include <cstdint>
#include <string.h>
#include <math.h>

#define TA 8192
#define TBB 8192
#define STG (2*TA + 2*TBB)
#define STAGES 3
#define SMEM_SZ (1024 + STAGES*STG)   // 99328 -> 2 CTAs/SM

// ---------------- device-global scratch ----------------
__device__ __align__(128) char g_qh[128*32*TA], g_ql[128*32*TA];
__device__ __align__(128) char g_kh[128*32*TA], g_kl[128*32*TA];
__device__ __align__(128) char g_vbh[4*8*128*TBB], g_vbl[4*8*128*TBB];
__device__ __align__(128) char g_wkh[8*32*TBB], g_wkl[8*32*TBB];
__device__ __align__(128) char g_woh[8*32*TBB], g_wol[8*32*TBB];
__device__ __align__(128) char g_wqh[8*32*TA],  g_wql[8*32*TA];
__device__ __align__(128) char g_wvh[8*32*TA],  g_wvl[8*32*TA];
__device__ __align__(128) char g_pkth[4*8*128*TA], g_pktl[4*8*128*TA];
__device__ __align__(128) char g_wvwoh[8*32*TBB], g_wvwol[8*32*TBB];
__device__ __align__(128) char g_kvrh[4*8*32*TA], g_kvrl[4*8*32*TA];
__device__ __align__(128) char g_kvoh[4*8*32*TBB], g_kvol[4*8*32*TBB];
__device__ __align__(128) char g_finh[4*8*32*TBB], g_finl[4*8*32*TBB];
__device__ unsigned int g_barA[2];
__device__ unsigned int g_barD[2];

// ---------------- PTX helpers ----------------
__device__ __forceinline__ uint32_t s2u(const void* p) {
    uint32_t a;
    asm("{ .reg .u64 t; cvta.to.shared.u64 t, %1; cvt.u32.u64 %0, t; }" : "=r"(a) : "l"(p));
    return a;
}
#define MBARRIER_INIT(addr, cnt) \
    asm volatile("mbarrier.init.shared.b64 [%0], %1;" :: "r"((uint32_t)(addr)), "r"((uint32_t)(cnt)) : "memory")
#define MBARRIER_EXPECT_TX(addr, bytes) \
    asm volatile("mbarrier.arrive.expect_tx.shared.b64 _, [%0], %1;" :: "r"((uint32_t)(addr)), "r"((uint32_t)(bytes)) : "memory")
#define MBARRIER_WAIT_PARITY(mbar, par) do { \
    uint32_t _m = (uint32_t)(mbar); uint32_t _p = (uint32_t)(par); uint32_t _d; \
    asm volatile("{\n\t.reg .pred p;\n\tmbarrier.try_wait.parity.acquire.cta.shared::cta.b64 p, [%1], %2;\n\tselp.b32 %0, 1, 0, p;\n\t}" \
        : "=r"(_d) : "r"(_m), "r"(_p) : "memory"); \
    if (!_d) { \
        asm volatile("{\n\t.reg .pred P1;\n\tWL_%=:\n\tmbarrier.try_wait.parity.acquire.cta.shared::cta.b64 P1, [%0], %1, 0x989680;\n\t@P1 bra.uni WD_%=;\n\tbra.uni WL_%=;\n\tWD_%=:\n\t}" \
            :: "r"(_m), "r"(_p) : "memory"); \
    } \
} while(0)

__device__ __forceinline__ void bulk_g2s(uint32_t dst, const void* src, uint32_t bytes, uint32_t mbar) {
    asm volatile("cp.async.bulk.shared::cluster.global.mbarrier::complete_tx::bytes [%0], [%1], %2, [%3];"
        :: "r"(dst), "l"(src), "r"(bytes), "r"(mbar) : "memory");
}
__device__ __forceinline__ void ldsm4(uint32_t* r, uint32_t a) {
    asm volatile("ldmatrix.sync.aligned.m8n8.x4.shared.b16 {%0,%1,%2,%3}, [%4];"
        : "=r"(r[0]), "=r"(r[1]), "=r"(r[2]), "=r"(r[3]) : "r"(a));
}
__device__ __forceinline__ void ldsm4t(uint32_t* r, uint32_t a) {
    asm volatile("ldmatrix.sync.aligned.m8n8.x4.trans.shared.b16 {%0,%1,%2,%3}, [%4];"
        : "=r"(r[0]), "=r"(r[1]), "=r"(r[2]), "=r"(r[3]) : "r"(a));
}
__device__ __forceinline__ void mma16816(float* c, const uint32_t* a, const uint32_t* b) {
    asm volatile("mma.sync.aligned.m16n8k16.row.col.f32.f16.f16.f32 "
        "{%0,%1,%2,%3}, {%4,%5,%6,%7}, {%8,%9}, {%0,%1,%2,%3};"
        : "+f"(c[0]), "+f"(c[1]), "+f"(c[2]), "+f"(c[3])
        : "r"(a[0]), "r"(a[1]), "r"(a[2]), "r"(a[3]), "r"(b[0]), "r"(b[1]));
}

__device__ __forceinline__ unsigned short hraw(__half h) { unsigned short u; memcpy(&u, &h, 2); return u; }
__device__ __forceinline__ void split2(float x, float y, uint32_t& H, uint32_t& L) {
    __half hx = __float2half_rn(x), hy = __float2half_rn(y);
    __half lx = __float2half_rn(x - __half2float(hx));
    __half ly = __float2half_rn(y - __half2float(hy));
    H = (uint32_t)hraw(hx) | ((uint32_t)hraw(hy) << 16);
    L = (uint32_t)hraw(lx) | ((uint32_t)hraw(ly) << 16);
}

__device__ __forceinline__ uint32_t a_off(int row, int kbyte) {
    int p = row >> 1;
    int c = (row & 1) * 4 + (kbyte >> 4);
    return (uint32_t)p * 128 + (uint32_t)((c ^ (p & 7)) * 16) + (kbyte & 15);
}
__device__ __forceinline__ uint32_t b_off(int r, int nbyte) {
    int q = nbyte >> 7;
    int c = (nbyte & 127) >> 4;
    return (uint32_t)q * 4096 + (uint32_t)r * 128 + (uint32_t)((c ^ (r & 7)) * 16) + (nbyte & 15);
}

// grid-wide barrier (n = total participating blocks)
__device__ __forceinline__ void grid_bar(int idx, unsigned int n) {
    __syncthreads();
    if (threadIdx.x == 0) {
        __threadfence();
        atomicAdd(&g_barA[idx], 1u);
        while (*((volatile unsigned int*)&g_barA[idx]) < n) __nanosleep(64);
        __threadfence();
        unsigned int d = atomicAdd(&g_barD[idx], 1u);
        if (d == n - 1) {
            *((volatile unsigned int*)&g_barA[idx]) = 0;
            __threadfence();
            *((volatile unsigned int*)&g_barD[idx]) = 0;
        }
    }
    __syncthreads();
}

// ---------------- conversion bodies ----------------
__device__ __forceinline__ void conv_unitA(const float* __restrict__ src, char* hi, char* lo, int idx) {
    int m = idx >> 7;
    int u0 = (idx & 127) << 3;
    const float4* s = reinterpret_cast<const float4*>(src + ((size_t)m << 10) + u0);
    float4 a = s[0], b = s[1];
    uint32_t h[4], l[4];
    split2(a.x, a.y, h[0], l[0]); split2(a.z, a.w, h[1], l[1]);
    split2(b.x, b.y, h[2], l[2]); split2(b.z, b.w, h[3], l[3]);
    size_t tile = ((size_t)(m >> 7) * 32 + (u0 >> 5)) * TA;
    uint32_t off = a_off(m & 127, (u0 & 31) * 2);
    *reinterpret_cast<uint4*>(hi + tile + off) = make_uint4(h[0], h[1], h[2], h[3]);
    *reinterpret_cast<uint4*>(lo + tile + off) = make_uint4(l[0], l[1], l[2], l[3]);
}
__device__ __forceinline__ void conv_unitV(const float* __restrict__ v, int idx) {
    int m = idx >> 7;
    int u0 = (idx & 127) << 3;
    const float4* s = reinterpret_cast<const float4*>(v + ((size_t)m << 10) + u0);
    float4 a = s[0], b = s[1];
    uint32_t h[4], l[4];
    split2(a.x, a.y, h[0], l[0]); split2(a.z, a.w, h[1], l[1]);
    split2(b.x, b.y, h[2], l[2]); split2(b.z, b.w, h[3], l[3]);
    int batch = m >> 12, sloc = m & 4095;
    size_t tile = ((size_t)(batch * 8 + (u0 >> 7)) * 128 + (sloc >> 5)) * TBB;
    uint32_t off = b_off(sloc & 31, (u0 & 127) * 2);
    *reinterpret_cast<uint4*>(g_vbh + tile + off) = make_uint4(h[0], h[1], h[2], h[3]);
    *reinterpret_cast<uint4*>(g_vbl + tile + off) = make_uint4(l[0], l[1], l[2], l[3]);
}

// Launch 1: k conv (blocks 0..8191) + 4 W convs (blocks 8192..10239)
__global__ void conv_kw(const float* __restrict__ key, const float* __restrict__ Wk,
                        const float* __restrict__ Wo, const float* __restrict__ Wq,
                        const float* __restrict__ Wv) {
    int bid = blockIdx.x;
    if (bid < 8192) {
        conv_unitA(key, g_kh, g_kl, bid * 256 + threadIdx.x);
        return;
    }
    int wb = bid - 8192;
    int zz = wb >> 9;
    int xb = wb & 511;
    const float* W = zz == 0 ? Wk : zz == 1 ? Wo : zz == 2 ? Wq : Wv;
    int idx = xb * 256 + threadIdx.x;
    int r = idx >> 7;
    int c0 = (idx & 127) << 3;
    const float4* s = reinterpret_cast<const float4*>(W + ((size_t)r << 10) + c0);
    float4 a = s[0], b = s[1];
    uint32_t h[4], l[4];
    split2(a.x, a.y, h[0], l[0]); split2(a.z, a.w, h[1], l[1]);
    split2(b.x, b.y, h[2], l[2]); split2(b.z, b.w, h[3], l[3]);
    if (zz < 2) {
        char* hi = zz == 0 ? g_wkh : g_woh;
        char* lo = zz == 0 ? g_wkl : g_wol;
        size_t tile = ((size_t)(c0 >> 7) * 32 + (r >> 5)) * TBB;
        uint32_t off = b_off(r & 31, (c0 & 127) * 2);
        *reinterpret_cast<uint4*>(hi + tile + off) = make_uint4(h[0], h[1], h[2], h[3]);
        *reinterpret_cast<uint4*>(lo + tile + off) = make_uint4(l[0], l[1], l[2], l[3]);
    } else {
        char* hi = zz == 2 ? g_wqh : g_wvh;
        char* lo = zz == 2 ? g_wql : g_wvl;
        size_t tile = ((size_t)(r >> 7) * 32 + (c0 >> 5)) * TA;
        uint32_t off = a_off(r & 127, (c0 & 31) * 2);
        *reinterpret_cast<uint4*>(hi + tile + off) = make_uint4(h[0], h[1], h[2], h[3]);
        *reinterpret_cast<uint4*>(lo + tile + off) = make_uint4(l[0], l[1], l[2], l[3]);
    }
}

// ---------------- shared GEMM mainloop ----------------
// TERMS=3: Ah*Bh + Al*Bh + Ah*Bl.  TERMS=2: Ah*Bh + Ah*Bl (Al not loaded).
template <int TERMS>
__device__ __forceinline__ void refill(uint32_t st0, uint32_t sb, int s,
        const char* Abh, const char* Abl, const char* Bbh, const char* Bbl, int c) {
    MBARRIER_EXPECT_TX(sb + 8 * s, TERMS == 3 ? STG : (STG - TA));
    uint32_t d = st0 + s * STG;
    bulk_g2s(d,            Abh + (size_t)c * TA,  TA,  sb + 8 * s);
    if (TERMS == 3)
        bulk_g2s(d + TA,   Abl + (size_t)c * TA,  TA,  sb + 8 * s);
    bulk_g2s(d + 2 * TA,   Bbh + (size_t)c * TBB, TBB, sb + 8 * s);
    bulk_g2s(d + 2*TA+TBB, Bbl + (size_t)c * TBB, TBB, sb + 8 * s);
}

template <int TERMS>
__device__ __forceinline__ void gemm_core(
        const char* __restrict__ Abh, const char* __restrict__ Abl,
        const char* __restrict__ Bbh, const char* __restrict__ Bbl,
        int kch, uint32_t sb, uint32_t st0, float acc[4][4][4]) {
    const int tid = threadIdx.x, lane = tid & 31, wid = tid >> 5;
    const int wm = wid >> 2, wn = wid & 3;
    const int i = lane & 15, h = lane >> 4;

    if (tid == 0)
        for (int s = 0; s < STAGES; ++s) MBARRIER_INIT(sb + 8 * s, 1);
    __syncthreads();

    if (tid == 0) {
        int np = STAGES < kch ? STAGES : kch;
        for (int s = 0; s < np; ++s) refill<TERMS>(st0, sb, s, Abh, Abl, Bbh, Bbl, s);
    }

#pragma unroll
    for (int ii = 0; ii < 4; ii++)
#pragma unroll
        for (int j = 0; j < 4; j++)
#pragma unroll
            for (int r = 0; r < 4; r++) acc[ii][j][r] = 0.0f;

    const uint32_t aBase = (uint32_t)wm * 4096 + (uint32_t)(i >> 1) * 128;
    const int xA = (i >> 1) & 7;
    const int cA0 = (i & 1) * 4 + h;
    const uint32_t qOff = (uint32_t)(wn >> 1) * 4096;
    const int xB = lane & 7;
    const uint32_t pj0 = (uint32_t)((((wn & 1) * 4 + h)     ^ xB) * 16);
    const uint32_t pj1 = (uint32_t)((((wn & 1) * 4 + h + 2) ^ xB) * 16);
    const uint32_t bRow = (uint32_t)i * 128;

    int s = 0, pf = 0;
    for (int c = 0; c < kch; ++c) {
        MBARRIER_WAIT_PARITY(sb + 8 * s, pf);
        uint32_t sa = st0 + s * STG;
#pragma unroll
        for (int k16 = 0; k16 < 2; ++k16) {
            uint32_t bb = sa + 2 * TA + qOff + bRow + k16 * 2048;
            uint32_t bh[4][2], bl4[4][2], t[4];
            ldsm4t(t, bb + pj0);        bh[0][0]=t[0]; bh[0][1]=t[1]; bh[1][0]=t[2]; bh[1][1]=t[3];
            ldsm4t(t, bb + pj1);        bh[2][0]=t[0]; bh[2][1]=t[1]; bh[3][0]=t[2]; bh[3][1]=t[3];
            ldsm4t(t, bb + TBB + pj0);  bl4[0][0]=t[0]; bl4[0][1]=t[1]; bl4[1][0]=t[2]; bl4[1][1]=t[3];
            ldsm4t(t, bb + TBB + pj1);  bl4[2][0]=t[0]; bl4[2][1]=t[1]; bl4[3][0]=t[2]; bl4[3][1]=t[3];
            uint32_t aoff = (uint32_t)(((cA0 + k16 * 2) ^ xA) * 16);
            uint32_t ab = sa + aBase + aoff;
#pragma unroll
            for (int mf = 0; mf < 4; ++mf) {
                uint32_t ah[4];
                ldsm4(ah, ab + mf * 1024);
                if (TERMS == 3) {
                    uint32_t al4[4];
                    ldsm4(al4, ab + TA + mf * 1024);
#pragma unroll
                    for (int nf = 0; nf < 4; ++nf) {
                        mma16816(acc[mf][nf], ah, bh[nf]);
                        mma16816(acc[mf][nf], al4, bh[nf]);
                        mma16816(acc[mf][nf], ah, bl4[nf]);
                    }
                } else {
#pragma unroll
                    for (int nf = 0; nf < 4; ++nf) {
                        mma16816(acc[mf][nf], ah, bh[nf]);
                        mma16816(acc[mf][nf], ah, bl4[nf]);
                    }
                }
            }
        }
        __syncthreads();
        if (tid == 0 && c + STAGES < kch)
            refill<TERMS>(st0, sb, s, Abh, Abl, Bbh, Bbl, c + STAGES);
        if (++s == STAGES) { s = 0; pf ^= 1; }
    }
}

// ---------------- epilogue helpers ----------------
__device__ __forceinline__ void epi_alayout(float acc[4][4][4], char* outH, char* outL,
                                            size_t mtile_base) {
    const int lane = threadIdx.x & 31, wid = threadIdx.x >> 5;
    const int wm = wid >> 2, wn = wid & 3;
    const int g = lane >> 2, tg = lane & 3;
    size_t mtile = (mtile_base + wn) * TA;
#pragma unroll
    for (int mf = 0; mf < 4; ++mf)
#pragma unroll
        for (int nf = 0; nf < 4; ++nf)
#pragma unroll
            for (int rh = 0; rh < 2; ++rh) {
                int row = wm * 64 + mf * 16 + g + rh * 8;
                uint32_t hw, lw;
                split2(acc[mf][nf][rh * 2], acc[mf][nf][rh * 2 + 1], hw, lw);
                uint32_t off = a_off(row, nf * 16 + tg * 4);
                *reinterpret_cast<uint32_t*>(outH + mtile + off) = hw;
                *reinterpret_cast<uint32_t*>(outL + mtile + off) = lw;
            }
}
__device__ __forceinline__ void epi_blayout(float acc[4][4][4], char* outH, char* outL,
                                            size_t nkbase, int m0) {
    const int lane = threadIdx.x & 31, wid = threadIdx.x >> 5;
    const int wm = wid >> 2, wn = wid & 3;
    const int g = lane >> 2, tg = lane & 3;
#pragma unroll
    for (int mf = 0; mf < 4; ++mf)
#pragma unroll
        for (int rh = 0; rh < 2; ++rh) {
            int row = wm * 64 + mf * 16 + g + rh * 8;
            int kloc = m0 + row;
            size_t tile = (nkbase + (kloc >> 5)) * TBB;
#pragma unroll
            for (int nf = 0; nf < 4; ++nf) {
                uint32_t hw, lw;
                split2(acc[mf][nf][rh * 2], acc[mf][nf][rh * 2 + 1], hw, lw);
                uint32_t off = b_off(kloc & 31, (wn * 32 + nf * 8 + tg * 2) * 2);
                *reinterpret_cast<uint32_t*>(outH + tile + off) = hw;
                *reinterpret_cast<uint32_t*>(outL + tile + off) = lw;
            }
        }
}

// ---------------- GEMM kernels ----------------
// blocks 0..1023: pk3T tiles; 1024..1087: WvWo; 1088..1599: conv(q); 1600..2111: conv(v)
__global__ void __launch_bounds__(256, 2)
projkB_gemm(const float* __restrict__ mask, const float* __restrict__ query,
            const float* __restrict__ value) {
    extern __shared__ __align__(1024) char smem[];
    uint32_t sb = s2u(smem), st0 = sb + 1024;
    const int tid = threadIdx.x, lane = tid & 31, wid = tid >> 5;
    const int wm = wid >> 2, wn = wid & 3;
    const int g = lane >> 2, tg = lane & 3;
    const int bid = blockIdx.x;

    if (bid >= 1088) {
        int cb = bid - 1088;
        if (cb < 512) {
#pragma unroll 1
            for (int it = 0; it < 16; ++it)
                conv_unitA(query, g_qh, g_ql, (cb * 16 + it) * 256 + tid);
        } else {
            cb -= 512;
#pragma unroll 1
            for (int it = 0; it < 16; ++it)
                conv_unitV(value, (cb * 16 + it) * 256 + tid);
        }
        return;
    }
    if (bid >= 1024) {
        int b2 = bid - 1024;
        int by = b2 >> 3, bx = b2 & 7;
        float acc[4][4][4];
        gemm_core<3>(g_wvh + (size_t)by * 32 * TA, g_wvl + (size_t)by * 32 * TA,
                     g_woh + (size_t)bx * 32 * TBB, g_wol + (size_t)bx * 32 * TBB,
                     32, sb, st0, acc);
        epi_blayout(acc, g_wvwoh, g_wvwol, (size_t)bx * 32, by * 128);
        return;
    }

    const int by = bid >> 3, bx = bid & 7;
    const int m0 = by * 128;

    float acc[4][4][4];
    gemm_core<3>(g_kh + (size_t)by * 32 * TA, g_kl + (size_t)by * 32 * TA,
                 g_wkh + (size_t)bx * 32 * TBB, g_wkl + (size_t)bx * 32 * TBB,
                 32, sb, st0, acc);
    __syncthreads();

    uint32_t shh = st0, sll = st0 + 34816;
#pragma unroll
    for (int mf = 0; mf < 4; ++mf)
#pragma unroll
        for (int rh = 0; rh < 2; ++rh) {
            int row = wm * 64 + mf * 16 + g + rh * 8;
            float mv = mask[m0 + row];
#pragma unroll
            for (int nf = 0; nf < 4; ++nf) {
                float v0 = acc[mf][nf][rh * 2] * mv;
                float v1 = acc[mf][nf][rh * 2 + 1] * mv;
                v0 = v0 / (1.0f + __expf(-v0)) * mv;
                v1 = v1 / (1.0f + __expf(-v1)) * mv;
                uint32_t hw, lw;
                split2(v0, v1, hw, lw);
                uint32_t a = (uint32_t)row * 272 + (wn * 32 + nf * 8 + tg * 2) * 2;
                asm volatile("st.shared.b32 [%0], %1;" :: "r"(shh + a), "r"(hw) : "memory");
                asm volatile("st.shared.b32 [%0], %1;" :: "r"(sll + a), "r"(lw) : "memory");
            }
        }
    __syncthreads();
    int u = tid & 127;
    int sh2 = (tid >> 7) * 64;
    int bt = by >> 5;
    int kc0 = (m0 & 4095) >> 5;
#pragma unroll
    for (int c8 = 0; c8 < 8; ++c8) {
        int s0 = sh2 + c8 * 8;
        uint32_t hw[4], lw[4];
#pragma unroll
        for (int p = 0; p < 4; ++p) {
            unsigned short h0, h1, l0, l1;
            uint32_t a0 = (uint32_t)(s0 + 2 * p) * 272 + (uint32_t)u * 2;
            uint32_t a1 = a0 + 272;
            asm volatile("ld.shared.b16 %0, [%1];" : "=h"(h0) : "r"(shh + a0));
            asm volatile("ld.shared.b16 %0, [%1];" : "=h"(h1) : "r"(shh + a1));
            asm volatile("ld.shared.b16 %0, [%1];" : "=h"(l0) : "r"(sll + a0));
            asm volatile("ld.shared.b16 %0, [%1];" : "=h"(l1) : "r"(sll + a1));
            hw[p] = (uint32_t)h0 | ((uint32_t)h1 << 16);
            lw[p] = (uint32_t)l0 | ((uint32_t)l1 << 16);
        }
        size_t tile = ((size_t)(bt * 8 + bx) * 128 + kc0 + (s0 >> 5)) * TA;
        uint32_t off = a_off(u, (s0 & 31) * 2);
        *reinterpret_cast<uint4*>(g_pkth + tile + off) = make_uint4(hw[0], hw[1], hw[2], hw[3]);
        *reinterpret_cast<uint4*>(g_pktl + tile + off) = make_uint4(lw[0], lw[1], lw[2], lw[3]);
    }
}

// Fused kvr -> kvo -> wqkvo, 256 blocks all resident. kvr uses 2-term fp16.
__global__ void __launch_bounds__(256, 2)
kvx_gemm() {
    extern __shared__ __align__(1024) char smem[];
    uint32_t sb = s2u(smem), st0 = sb + 1024;
    const int bid = blockIdx.x;
    const int b = bid >> 6, by = (bid >> 3) & 7, bx = bid & 7;

    float acc[4][4][4];
    // Phase 1: kvr[b] = pk3T[b] @ v[b]  (K=4096) -- 2-term (drop pk's low x v's high)
    gemm_core<2>(g_pkth + (size_t)(b * 8 + by) * 128 * TA, g_pktl + (size_t)(b * 8 + by) * 128 * TA,
                 g_vbh + (size_t)(b * 8 + bx) * 128 * TBB, g_vbl + (size_t)(b * 8 + bx) * 128 * TBB,
                 128, sb, st0, acc);
    epi_alayout(acc, g_kvrh, g_kvrl, (size_t)(b * 8 + by) * 32 + bx * 4);

    grid_bar(0, 256);

    gemm_core<3>(g_kvrh + (size_t)(b * 8 + by) * 32 * TA, g_kvrl + (size_t)(b * 8 + by) * 32 * TA,
                 g_wvwoh + (size_t)bx * 32 * TBB, g_wvwol + (size_t)bx * 32 * TBB,
                 32, sb, st0, acc);
    epi_blayout(acc, g_kvoh, g_kvol, (size_t)(b * 8 + bx) * 32, by * 128);

    grid_bar(1, 256);

    gemm_core<3>(g_wqh + (size_t)by * 32 * TA, g_wql + (size_t)by * 32 * TA,
                 g_kvoh + (size_t)(b * 8 + bx) * 32 * TBB, g_kvol + (size_t)(b * 8 + bx) * 32 * TBB,
                 32, sb, st0, acc);
    epi_blayout(acc, g_finh, g_finl, (size_t)(b * 8 + bx) * 32, by * 128);
}

// out[b] = q[b] @ fin[b] -> f32
__global__ void __launch_bounds__(256, 2)
final_gemm(float* __restrict__ outF) {
    extern __shared__ __align__(1024) char smem[];
    uint32_t sb = s2u(smem), st0 = sb + 1024;
    const int tid = threadIdx.x, lane = tid & 31, wid = tid >> 5;
    const int wm = wid >> 2, wn = wid & 3;
    const int bx = blockIdx.x, by = blockIdx.y, z = blockIdx.z;
    const int g = lane >> 2, tg = lane & 3;
    const int mb = z * 32 + by;
    const int n0 = bx * 128;

    float acc[4][4][4];
    gemm_core<3>(g_qh + (size_t)mb * 32 * TA, g_ql + (size_t)mb * 32 * TA,
                 g_finh + (size_t)(z * 8 + bx) * 32 * TBB, g_finl + (size_t)(z * 8 + bx) * 32 * TBB,
                 32, sb, st0, acc);

#pragma unroll
    for (int mf = 0; mf < 4; ++mf)
#pragma unroll
        for (int nf = 0; nf < 4; ++nf)
#pragma unroll
            for (int rh = 0; rh < 2; ++rh) {
                int row = wm * 64 + mf * 16 + g + rh * 8;
                int gcol = n0 + wn * 32 + nf * 8 + tg * 2;
                float2 v = make_float2(acc[mf][nf][rh * 2], acc[mf][nf][rh * 2 + 1]);
                *reinterpret_cast<float2*>(outF + ((size_t)mb * 128 + row) * 1024 + gcol) = v;
            }
}

// ---------------- launch ----------------
extern "C" void kernel_launch(void* const* d_in, const int* in_sizes, int n_in,
                              void* d_out, int out_size) {
    const float* query = (const float*)d_in[0];
    const float* key   = (const float*)d_in[1];
    const float* value = (const float*)d_in[2];
    const float* mask  = (const float*)d_in[3];
    const float* Wk    = (const float*)d_in[4];
    const float* Wv    = (const float*)d_in[5];
    const float* Wq    = (const float*)d_in[6];
    const float* Wo    = (const float*)d_in[7];
    float* out = (float*)d_out;

    static bool attr_done = false;
    if (!attr_done) {
        cudaFuncSetAttribute(projkB_gemm, cudaFuncAttributeMaxDynamicSharedMemorySize, SMEM_SZ);
        cudaFuncSetAttribute(kvx_gemm,    cudaFuncAttributeMaxDynamicSharedMemorySize, SMEM_SZ);
        cudaFuncSetAttribute(final_gemm,  cudaFuncAttributeMaxDynamicSharedMemorySize, SMEM_SZ);
        attr_done = true;
    }

    conv_kw<<<10240, 256>>>(key, Wk, Wo, Wq, Wv);
    projkB_gemm<<<2112, 256, SMEM_SZ>>>(mask, query, value);
    kvx_gemm<<<256, 256, SMEM_SZ>>>();
    final_gemm<<<dim3(8, 32, 4), 256, SMEM_SZ>>>(out);
}

// round 16
// speedup vs baseline: 1.3373x; 1.1541x over previous
#include <cuda_runtime.h>
#include <cuda_bf16.h>
#include <cuda_fp16.h>
#include <cstdint>
#include <string.h>
#include <math.h>

#define TA 8192
#define TBB 8192
#define STG (2*TA + 2*TBB)
#define STAGES 3
#define SMEM_SZ (1024 + STAGES*STG)   // 99328 -> 2 CTAs/SM

// ---------------- device-global scratch ----------------
__device__ __align__(128) char g_qh[128*32*TA], g_ql[128*32*TA];
__device__ __align__(128) char g_kh[128*32*TA], g_kl[128*32*TA];
__device__ __align__(128) char g_vbh[4*8*128*TBB], g_vbl[4*8*128*TBB];
__device__ __align__(128) char g_wkh[8*32*TBB], g_wkl[8*32*TBB];
__device__ __align__(128) char g_woh[8*32*TBB], g_wol[8*32*TBB];
__device__ __align__(128) char g_wqh[8*32*TA],  g_wql[8*32*TA];
__device__ __align__(128) char g_wvh[8*32*TA],  g_wvl[8*32*TA];
__device__ __align__(128) char g_pkth[4*8*128*TA], g_pktl[4*8*128*TA];
__device__ __align__(128) char g_wvwoh[8*32*TBB], g_wvwol[8*32*TBB];
__device__ __align__(128) char g_kvrh[4*8*32*TA], g_kvrl[4*8*32*TA];
__device__ __align__(128) char g_kvoh[4*8*32*TBB], g_kvol[4*8*32*TBB];
__device__ __align__(128) char g_finh[4*8*32*TBB], g_finl[4*8*32*TBB];
__device__ unsigned int g_barA[2];
__device__ unsigned int g_barD[2];

// ---------------- PTX helpers ----------------
__device__ __forceinline__ uint32_t s2u(const void* p) {
    uint32_t a;
    asm("{ .reg .u64 t; cvta.to.shared.u64 t, %1; cvt.u32.u64 %0, t; }" : "=r"(a) : "l"(p));
    return a;
}
#define MBARRIER_INIT(addr, cnt) \
    asm volatile("mbarrier.init.shared.b64 [%0], %1;" :: "r"((uint32_t)(addr)), "r"((uint32_t)(cnt)) : "memory")
#define MBARRIER_EXPECT_TX(addr, bytes) \
    asm volatile("mbarrier.arrive.expect_tx.shared.b64 _, [%0], %1;" :: "r"((uint32_t)(addr)), "r"((uint32_t)(bytes)) : "memory")
#define MBARRIER_WAIT_PARITY(mbar, par) do { \
    uint32_t _m = (uint32_t)(mbar); uint32_t _p = (uint32_t)(par); uint32_t _d; \
    asm volatile("{\n\t.reg .pred p;\n\tmbarrier.try_wait.parity.acquire.cta.shared::cta.b64 p, [%1], %2;\n\tselp.b32 %0, 1, 0, p;\n\t}" \
        : "=r"(_d) : "r"(_m), "r"(_p) : "memory"); \
    if (!_d) { \
        asm volatile("{\n\t.reg .pred P1;\n\tWL_%=:\n\tmbarrier.try_wait.parity.acquire.cta.shared::cta.b64 P1, [%0], %1, 0x989680;\n\t@P1 bra.uni WD_%=;\n\tbra.uni WL_%=;\n\tWD_%=:\n\t}" \
            :: "r"(_m), "r"(_p) : "memory"); \
    } \
} while(0)

__device__ __forceinline__ void bulk_g2s(uint32_t dst, const void* src, uint32_t bytes, uint32_t mbar) {
    asm volatile("cp.async.bulk.shared::cluster.global.mbarrier::complete_tx::bytes [%0], [%1], %2, [%3];"
        :: "r"(dst), "l"(src), "r"(bytes), "r"(mbar) : "memory");
}
__device__ __forceinline__ void ldsm4(uint32_t* r, uint32_t a) {
    asm volatile("ldmatrix.sync.aligned.m8n8.x4.shared.b16 {%0,%1,%2,%3}, [%4];"
        : "=r"(r[0]), "=r"(r[1]), "=r"(r[2]), "=r"(r[3]) : "r"(a));
}
__device__ __forceinline__ void ldsm4t(uint32_t* r, uint32_t a) {
    asm volatile("ldmatrix.sync.aligned.m8n8.x4.trans.shared.b16 {%0,%1,%2,%3}, [%4];"
        : "=r"(r[0]), "=r"(r[1]), "=r"(r[2]), "=r"(r[3]) : "r"(a));
}
__device__ __forceinline__ void mma16816(float* c, const uint32_t* a, const uint32_t* b) {
    asm volatile("mma.sync.aligned.m16n8k16.row.col.f32.f16.f16.f32 "
        "{%0,%1,%2,%3}, {%4,%5,%6,%7}, {%8,%9}, {%0,%1,%2,%3};"
        : "+f"(c[0]), "+f"(c[1]), "+f"(c[2]), "+f"(c[3])
        : "r"(a[0]), "r"(a[1]), "r"(a[2]), "r"(a[3]), "r"(b[0]), "r"(b[1]));
}

__device__ __forceinline__ unsigned short hraw(__half h) { unsigned short u; memcpy(&u, &h, 2); return u; }
__device__ __forceinline__ void split2(float x, float y, uint32_t& H, uint32_t& L) {
    __half hx = __float2half_rn(x), hy = __float2half_rn(y);
    __half lx = __float2half_rn(x - __half2float(hx));
    __half ly = __float2half_rn(y - __half2float(hy));
    H = (uint32_t)hraw(hx) | ((uint32_t)hraw(hy) << 16);
    L = (uint32_t)hraw(lx) | ((uint32_t)hraw(ly) << 16);
}

__device__ __forceinline__ uint32_t a_off(int row, int kbyte) {
    int p = row >> 1;
    int c = (row & 1) * 4 + (kbyte >> 4);
    return (uint32_t)p * 128 + (uint32_t)((c ^ (p & 7)) * 16) + (kbyte & 15);
}
__device__ __forceinline__ uint32_t b_off(int r, int nbyte) {
    int q = nbyte >> 7;
    int c = (nbyte & 127) >> 4;
    return (uint32_t)q * 4096 + (uint32_t)r * 128 + (uint32_t)((c ^ (r & 7)) * 16) + (nbyte & 15);
}

// grid-wide barrier (n = total participating blocks)
__device__ __forceinline__ void grid_bar(int idx, unsigned int n) {
    __syncthreads();
    if (threadIdx.x == 0) {
        __threadfence();
        atomicAdd(&g_barA[idx], 1u);
        while (*((volatile unsigned int*)&g_barA[idx]) < n) __nanosleep(64);
        __threadfence();
        unsigned int d = atomicAdd(&g_barD[idx], 1u);
        if (d == n - 1) {
            *((volatile unsigned int*)&g_barA[idx]) = 0;
            __threadfence();
            *((volatile unsigned int*)&g_barD[idx]) = 0;
        }
    }
    __syncthreads();
}

// ---------------- conversion bodies ----------------
__device__ __forceinline__ void conv_unitA(const float* __restrict__ src, char* hi, char* lo, int idx) {
    int m = idx >> 7;
    int u0 = (idx & 127) << 3;
    const float4* s = reinterpret_cast<const float4*>(src + ((size_t)m << 10) + u0);
    float4 a = s[0], b = s[1];
    uint32_t h[4], l[4];
    split2(a.x, a.y, h[0], l[0]); split2(a.z, a.w, h[1], l[1]);
    split2(b.x, b.y, h[2], l[2]); split2(b.z, b.w, h[3], l[3]);
    size_t tile = ((size_t)(m >> 7) * 32 + (u0 >> 5)) * TA;
    uint32_t off = a_off(m & 127, (u0 & 31) * 2);
    *reinterpret_cast<uint4*>(hi + tile + off) = make_uint4(h[0], h[1], h[2], h[3]);
    *reinterpret_cast<uint4*>(lo + tile + off) = make_uint4(l[0], l[1], l[2], l[3]);
}
__device__ __forceinline__ void conv_unitV(const float* __restrict__ v, int idx) {
    int m = idx >> 7;
    int u0 = (idx & 127) << 3;
    const float4* s = reinterpret_cast<const float4*>(v + ((size_t)m << 10) + u0);
    float4 a = s[0], b = s[1];
    uint32_t h[4], l[4];
    split2(a.x, a.y, h[0], l[0]); split2(a.z, a.w, h[1], l[1]);
    split2(b.x, b.y, h[2], l[2]); split2(b.z, b.w, h[3], l[3]);
    int batch = m >> 12, sloc = m & 4095;
    size_t tile = ((size_t)(batch * 8 + (u0 >> 7)) * 128 + (sloc >> 5)) * TBB;
    uint32_t off = b_off(sloc & 31, (u0 & 127) * 2);
    *reinterpret_cast<uint4*>(g_vbh + tile + off) = make_uint4(h[0], h[1], h[2], h[3]);
    *reinterpret_cast<uint4*>(g_vbl + tile + off) = make_uint4(l[0], l[1], l[2], l[3]);
}

// Launch 1: k conv (blocks 0..8191) + 4 W convs (blocks 8192..10239)
__global__ void conv_kw(const float* __restrict__ key, const float* __restrict__ Wk,
                        const float* __restrict__ Wo, const float* __restrict__ Wq,
                        const float* __restrict__ Wv) {
    int bid = blockIdx.x;
    if (bid < 8192) {
        conv_unitA(key, g_kh, g_kl, bid * 256 + threadIdx.x);
        return;
    }
    int wb = bid - 8192;
    int zz = wb >> 9;
    int xb = wb & 511;
    const float* W = zz == 0 ? Wk : zz == 1 ? Wo : zz == 2 ? Wq : Wv;
    int idx = xb * 256 + threadIdx.x;
    int r = idx >> 7;
    int c0 = (idx & 127) << 3;
    const float4* s = reinterpret_cast<const float4*>(W + ((size_t)r << 10) + c0);
    float4 a = s[0], b = s[1];
    uint32_t h[4], l[4];
    split2(a.x, a.y, h[0], l[0]); split2(a.z, a.w, h[1], l[1]);
    split2(b.x, b.y, h[2], l[2]); split2(b.z, b.w, h[3], l[3]);
    if (zz < 2) {
        char* hi = zz == 0 ? g_wkh : g_woh;
        char* lo = zz == 0 ? g_wkl : g_wol;
        size_t tile = ((size_t)(c0 >> 7) * 32 + (r >> 5)) * TBB;
        uint32_t off = b_off(r & 31, (c0 & 127) * 2);
        *reinterpret_cast<uint4*>(hi + tile + off) = make_uint4(h[0], h[1], h[2], h[3]);
        *reinterpret_cast<uint4*>(lo + tile + off) = make_uint4(l[0], l[1], l[2], l[3]);
    } else {
        char* hi = zz == 2 ? g_wqh : g_wvh;
        char* lo = zz == 2 ? g_wql : g_wvl;
        size_t tile = ((size_t)(r >> 7) * 32 + (c0 >> 5)) * TA;
        uint32_t off = a_off(r & 127, (c0 & 31) * 2);
        *reinterpret_cast<uint4*>(hi + tile + off) = make_uint4(h[0], h[1], h[2], h[3]);
        *reinterpret_cast<uint4*>(lo + tile + off) = make_uint4(l[0], l[1], l[2], l[3]);
    }
}

// ---------------- shared GEMM mainloop ----------------
// TERMS=3: Ah*Bh + Al*Bh + Ah*Bl.  TERMS=2: Ah*Bh + Ah*Bl (Al not loaded).
template <int TERMS>
__device__ __forceinline__ void refill(uint32_t st0, uint32_t sb, int s,
        const char* Abh, const char* Abl, const char* Bbh, const char* Bbl, int c) {
    MBARRIER_EXPECT_TX(sb + 8 * s, TERMS == 3 ? STG : (STG - TA));
    uint32_t d = st0 + s * STG;
    bulk_g2s(d,            Abh + (size_t)c * TA,  TA,  sb + 8 * s);
    if (TERMS == 3)
        bulk_g2s(d + TA,   Abl + (size_t)c * TA,  TA,  sb + 8 * s);
    bulk_g2s(d + 2 * TA,   Bbh + (size_t)c * TBB, TBB, sb + 8 * s);
    bulk_g2s(d + 2*TA+TBB, Bbl + (size_t)c * TBB, TBB, sb + 8 * s);
}

template <int TERMS>
__device__ __forceinline__ void gemm_core(
        const char* __restrict__ Abh, const char* __restrict__ Abl,
        const char* __restrict__ Bbh, const char* __restrict__ Bbl,
        int kch, uint32_t sb, uint32_t st0, float acc[4][4][4]) {
    const int tid = threadIdx.x, lane = tid & 31, wid = tid >> 5;
    const int wm = wid >> 2, wn = wid & 3;
    const int i = lane & 15, h = lane >> 4;

    if (tid == 0)
        for (int s = 0; s < STAGES; ++s) MBARRIER_INIT(sb + 8 * s, 1);
    __syncthreads();

    if (tid == 0) {
        int np = STAGES < kch ? STAGES : kch;
        for (int s = 0; s < np; ++s) refill<TERMS>(st0, sb, s, Abh, Abl, Bbh, Bbl, s);
    }

#pragma unroll
    for (int ii = 0; ii < 4; ii++)
#pragma unroll
        for (int j = 0; j < 4; j++)
#pragma unroll
            for (int r = 0; r < 4; r++) acc[ii][j][r] = 0.0f;

    const uint32_t aBase = (uint32_t)wm * 4096 + (uint32_t)(i >> 1) * 128;
    const int xA = (i >> 1) & 7;
    const int cA0 = (i & 1) * 4 + h;
    const uint32_t qOff = (uint32_t)(wn >> 1) * 4096;
    const int xB = lane & 7;
    const uint32_t pj0 = (uint32_t)((((wn & 1) * 4 + h)     ^ xB) * 16);
    const uint32_t pj1 = (uint32_t)((((wn & 1) * 4 + h + 2) ^ xB) * 16);
    const uint32_t bRow = (uint32_t)i * 128;

    int s = 0, pf = 0;
    for (int c = 0; c < kch; ++c) {
        MBARRIER_WAIT_PARITY(sb + 8 * s, pf);
        uint32_t sa = st0 + s * STG;
#pragma unroll
        for (int k16 = 0; k16 < 2; ++k16) {
            uint32_t bb = sa + 2 * TA + qOff + bRow + k16 * 2048;
            uint32_t bh[4][2], bl4[4][2], t[4];
            ldsm4t(t, bb + pj0);        bh[0][0]=t[0]; bh[0][1]=t[1]; bh[1][0]=t[2]; bh[1][1]=t[3];
            ldsm4t(t, bb + pj1);        bh[2][0]=t[0]; bh[2][1]=t[1]; bh[3][0]=t[2]; bh[3][1]=t[3];
            ldsm4t(t, bb + TBB + pj0);  bl4[0][0]=t[0]; bl4[0][1]=t[1]; bl4[1][0]=t[2]; bl4[1][1]=t[3];
            ldsm4t(t, bb + TBB + pj1);  bl4[2][0]=t[0]; bl4[2][1]=t[1]; bl4[3][0]=t[2]; bl4[3][1]=t[3];
            uint32_t aoff = (uint32_t)(((cA0 + k16 * 2) ^ xA) * 16);
            uint32_t ab = sa + aBase + aoff;
#pragma unroll
            for (int mf = 0; mf < 4; ++mf) {
                uint32_t ah[4];
                ldsm4(ah, ab + mf * 1024);
                if (TERMS == 3) {
                    uint32_t al4[4];
                    ldsm4(al4, ab + TA + mf * 1024);
#pragma unroll
                    for (int nf = 0; nf < 4; ++nf) {
                        mma16816(acc[mf][nf], ah, bh[nf]);
                        mma16816(acc[mf][nf], al4, bh[nf]);
                        mma16816(acc[mf][nf], ah, bl4[nf]);
                    }
                } else {
#pragma unroll
                    for (int nf = 0; nf < 4; ++nf) {
                        mma16816(acc[mf][nf], ah, bh[nf]);
                        mma16816(acc[mf][nf], ah, bl4[nf]);
                    }
                }
            }
        }
        __syncthreads();
        if (tid == 0 && c + STAGES < kch)
            refill<TERMS>(st0, sb, s, Abh, Abl, Bbh, Bbl, c + STAGES);
        if (++s == STAGES) { s = 0; pf ^= 1; }
    }
}

// ---------------- epilogue helpers ----------------
__device__ __forceinline__ void epi_alayout(float acc[4][4][4], char* outH, char* outL,
                                            size_t mtile_base) {
    const int lane = threadIdx.x & 31, wid = threadIdx.x >> 5;
    const int wm = wid >> 2, wn = wid & 3;
    const int g = lane >> 2, tg = lane & 3;
    size_t mtile = (mtile_base + wn) * TA;
#pragma unroll
    for (int mf = 0; mf < 4; ++mf)
#pragma unroll
        for (int nf = 0; nf < 4; ++nf)
#pragma unroll
            for (int rh = 0; rh < 2; ++rh) {
                int row = wm * 64 + mf * 16 + g + rh * 8;
                uint32_t hw, lw;
                split2(acc[mf][nf][rh * 2], acc[mf][nf][rh * 2 + 1], hw, lw);
                uint32_t off = a_off(row, nf * 16 + tg * 4);
                *reinterpret_cast<uint32_t*>(outH + mtile + off) = hw;
                *reinterpret_cast<uint32_t*>(outL + mtile + off) = lw;
            }
}
__device__ __forceinline__ void epi_blayout(float acc[4][4][4], char* outH, char* outL,
                                            size_t nkbase, int m0) {
    const int lane = threadIdx.x & 31, wid = threadIdx.x >> 5;
    const int wm = wid >> 2, wn = wid & 3;
    const int g = lane >> 2, tg = lane & 3;
#pragma unroll
    for (int mf = 0; mf < 4; ++mf)
#pragma unroll
        for (int rh = 0; rh < 2; ++rh) {
            int row = wm * 64 + mf * 16 + g + rh * 8;
            int kloc = m0 + row;
            size_t tile = (nkbase + (kloc >> 5)) * TBB;
#pragma unroll
            for (int nf = 0; nf < 4; ++nf) {
                uint32_t hw, lw;
                split2(acc[mf][nf][rh * 2], acc[mf][nf][rh * 2 + 1], hw, lw);
                uint32_t off = b_off(kloc & 31, (wn * 32 + nf * 8 + tg * 2) * 2);
                *reinterpret_cast<uint32_t*>(outH + tile + off) = hw;
                *reinterpret_cast<uint32_t*>(outL + tile + off) = lw;
            }
        }
}

// ---------------- GEMM kernels ----------------
// blocks 0..1023: pk3T tiles (2-term); 1024..1087: WvWo; 1088..1599: conv(q); 1600..2111: conv(v)
__global__ void __launch_bounds__(256, 2)
projkB_gemm(const float* __restrict__ mask, const float* __restrict__ query,
            const float* __restrict__ value) {
    extern __shared__ __align__(1024) char smem[];
    uint32_t sb = s2u(smem), st0 = sb + 1024;
    const int tid = threadIdx.x, lane = tid & 31, wid = tid >> 5;
    const int wm = wid >> 2, wn = wid & 3;
    const int g = lane >> 2, tg = lane & 3;
    const int bid = blockIdx.x;

    if (bid >= 1088) {
        int cb = bid - 1088;
        if (cb < 512) {
#pragma unroll 1
            for (int it = 0; it < 16; ++it)
                conv_unitA(query, g_qh, g_ql, (cb * 16 + it) * 256 + tid);
        } else {
            cb -= 512;
#pragma unroll 1
            for (int it = 0; it < 16; ++it)
                conv_unitV(value, (cb * 16 + it) * 256 + tid);
        }
        return;
    }
    if (bid >= 1024) {
        int b2 = bid - 1024;
        int by = b2 >> 3, bx = b2 & 7;
        float acc[4][4][4];
        gemm_core<3>(g_wvh + (size_t)by * 32 * TA, g_wvl + (size_t)by * 32 * TA,
                     g_woh + (size_t)bx * 32 * TBB, g_wol + (size_t)bx * 32 * TBB,
                     32, sb, st0, acc);
        epi_blayout(acc, g_wvwoh, g_wvwol, (size_t)bx * 32, by * 128);
        return;
    }

    const int by = bid >> 3, bx = bid & 7;
    const int m0 = by * 128;

    float acc[4][4][4];
    gemm_core<2>(g_kh + (size_t)by * 32 * TA, g_kl + (size_t)by * 32 * TA,
                 g_wkh + (size_t)bx * 32 * TBB, g_wkl + (size_t)bx * 32 * TBB,
                 32, sb, st0, acc);
    __syncthreads();

    uint32_t shh = st0, sll = st0 + 34816;
#pragma unroll
    for (int mf = 0; mf < 4; ++mf)
#pragma unroll
        for (int rh = 0; rh < 2; ++rh) {
            int row = wm * 64 + mf * 16 + g + rh * 8;
            float mv = mask[m0 + row];
#pragma unroll
            for (int nf = 0; nf < 4; ++nf) {
                float v0 = acc[mf][nf][rh * 2] * mv;
                float v1 = acc[mf][nf][rh * 2 + 1] * mv;
                v0 = v0 / (1.0f + __expf(-v0)) * mv;
                v1 = v1 / (1.0f + __expf(-v1)) * mv;
                uint32_t hw, lw;
                split2(v0, v1, hw, lw);
                uint32_t a = (uint32_t)row * 272 + (wn * 32 + nf * 8 + tg * 2) * 2;
                asm volatile("st.shared.b32 [%0], %1;" :: "r"(shh + a), "r"(hw) : "memory");
                asm volatile("st.shared.b32 [%0], %1;" :: "r"(sll + a), "r"(lw) : "memory");
            }
        }
    __syncthreads();
    int u = tid & 127;
    int sh2 = (tid >> 7) * 64;
    int bt = by >> 5;
    int kc0 = (m0 & 4095) >> 5;
#pragma unroll
    for (int c8 = 0; c8 < 8; ++c8) {
        int s0 = sh2 + c8 * 8;
        uint32_t hw[4], lw[4];
#pragma unroll
        for (int p = 0; p < 4; ++p) {
            unsigned short h0, h1, l0, l1;
            uint32_t a0 = (uint32_t)(s0 + 2 * p) * 272 + (uint32_t)u * 2;
            uint32_t a1 = a0 + 272;
            asm volatile("ld.shared.b16 %0, [%1];" : "=h"(h0) : "r"(shh + a0));
            asm volatile("ld.shared.b16 %0, [%1];" : "=h"(h1) : "r"(shh + a1));
            asm volatile("ld.shared.b16 %0, [%1];" : "=h"(l0) : "r"(sll + a0));
            asm volatile("ld.shared.b16 %0, [%1];" : "=h"(l1) : "r"(sll + a1));
            hw[p] = (uint32_t)h0 | ((uint32_t)h1 << 16);
            lw[p] = (uint32_t)l0 | ((uint32_t)l1 << 16);
        }
        size_t tile = ((size_t)(bt * 8 + bx) * 128 + kc0 + (s0 >> 5)) * TA;
        uint32_t off = a_off(u, (s0 & 31) * 2);
        *reinterpret_cast<uint4*>(g_pkth + tile + off) = make_uint4(hw[0], hw[1], hw[2], hw[3]);
        *reinterpret_cast<uint4*>(g_pktl + tile + off) = make_uint4(lw[0], lw[1], lw[2], lw[3]);
    }
}

// Fused kvr -> kvo -> wqkvo, 256 blocks all resident. kvr uses 2-term fp16.
__global__ void __launch_bounds__(256, 2)
kvx_gemm() {
    extern __shared__ __align__(1024) char smem[];
    uint32_t sb = s2u(smem), st0 = sb + 1024;
    const int bid = blockIdx.x;
    const int b = bid >> 6, by = (bid >> 3) & 7, bx = bid & 7;

    float acc[4][4][4];
    gemm_core<2>(g_pkth + (size_t)(b * 8 + by) * 128 * TA, g_pktl + (size_t)(b * 8 + by) * 128 * TA,
                 g_vbh + (size_t)(b * 8 + bx) * 128 * TBB, g_vbl + (size_t)(b * 8 + bx) * 128 * TBB,
                 128, sb, st0, acc);
    epi_alayout(acc, g_kvrh, g_kvrl, (size_t)(b * 8 + by) * 32 + bx * 4);

    grid_bar(0, 256);

    gemm_core<3>(g_kvrh + (size_t)(b * 8 + by) * 32 * TA, g_kvrl + (size_t)(b * 8 + by) * 32 * TA,
                 g_wvwoh + (size_t)bx * 32 * TBB, g_wvwol + (size_t)bx * 32 * TBB,
                 32, sb, st0, acc);
    epi_blayout(acc, g_kvoh, g_kvol, (size_t)(b * 8 + bx) * 32, by * 128);

    grid_bar(1, 256);

    gemm_core<3>(g_wqh + (size_t)by * 32 * TA, g_wql + (size_t)by * 32 * TA,
                 g_kvoh + (size_t)(b * 8 + bx) * 32 * TBB, g_kvol + (size_t)(b * 8 + bx) * 32 * TBB,
                 32, sb, st0, acc);
    epi_blayout(acc, g_finh, g_finl, (size_t)(b * 8 + bx) * 32, by * 128);
}

// out[b] = q[b] @ fin[b] -> f32 (2-term)
__global__ void __launch_bounds__(256, 2)
final_gemm(float* __restrict__ outF) {
    extern __shared__ __align__(1024) char smem[];
    uint32_t sb = s2u(smem), st0 = sb + 1024;
    const int tid = threadIdx.x, lane = tid & 31, wid = tid >> 5;
    const int wm = wid >> 2, wn = wid & 3;
    const int bx = blockIdx.x, by = blockIdx.y, z = blockIdx.z;
    const int g = lane >> 2, tg = lane & 3;
    const int mb = z * 32 + by;
    const int n0 = bx * 128;

    float acc[4][4][4];
    gemm_core<2>(g_qh + (size_t)mb * 32 * TA, g_ql + (size_t)mb * 32 * TA,
                 g_finh + (size_t)(z * 8 + bx) * 32 * TBB, g_finl + (size_t)(z * 8 + bx) * 32 * TBB,
                 32, sb, st0, acc);

#pragma unroll
    for (int mf = 0; mf < 4; ++mf)
#pragma unroll
        for (int nf = 0; nf < 4; ++nf)
#pragma unroll
            for (int rh = 0; rh < 2; ++rh) {
                int row = wm * 64 + mf * 16 + g + rh * 8;
                int gcol = n0 + wn * 32 + nf * 8 + tg * 2;
                float2 v = make_float2(acc[mf][nf][rh * 2], acc[mf][nf][rh * 2 + 1]);
                *reinterpret_cast<float2*>(outF + ((size_t)mb * 128 + row) * 1024 + gcol) = v;
            }
}

// ---------------- launch ----------------
extern "C" void kernel_launch(void* const* d_in, const int* in_sizes, int n_in,
                              void* d_out, int out_size) {
    const float* query = (const float*)d_in[0];
    const float* key   = (const float*)d_in[1];
    const float* value = (const float*)d_in[2];
    const float* mask  = (const float*)d_in[3];
    const float* Wk    = (const float*)d_in[4];
    const float* Wv    = (const float*)d_in[5];
    const float* Wq    = (const float*)d_in[6];
    const float* Wo    = (const float*)d_in[7];
    float* out = (float*)d_out;

    static bool attr_done = false;
    if (!attr_done) {
        cudaFuncSetAttribute(projkB_gemm, cudaFuncAttributeMaxDynamicSharedMemorySize, SMEM_SZ);
        cudaFuncSetAttribute(kvx_gemm,    cudaFuncAttributeMaxDynamicSharedMemorySize, SMEM_SZ);
        cudaFuncSetAttribute(final_gemm,  cudaFuncAttributeMaxDynamicSharedMemorySize, SMEM_SZ);
        attr_done = true;
    }

    conv_kw<<<10240, 256>>>(key, Wk, Wo, Wq, Wv);
    projkB_gemm<<<2112, 256, SMEM_SZ>>>(mask, query, value);
    kvx_gemm<<<256, 256, SMEM_SZ>>>();
    final_gemm<<<dim3(8, 32, 4), 256, SMEM_SZ>>>(out);
}

// round 17
// speedup vs baseline: 1.4137x; 1.0572x over previous
#include <cuda_runtime.h>
#include <cuda_bf16.h>
#include <cuda_fp16.h>
#include <cstdint>
#include <string.h>
#include <math.h>

#define TA 8192
#define TBB 8192
#define STG (2*TA + 2*TBB)
#define STAGES 3
#define SMEM_SZ (1024 + STAGES*STG)   // 99328 -> 2 CTAs/SM

// ---------------- device-global scratch ----------------
__device__ __align__(128) char g_qh[128*32*TA], g_ql[128*32*TA];
__device__ __align__(128) char g_kh[128*32*TA], g_kl[128*32*TA];
__device__ __align__(128) char g_vbh[4*8*128*TBB], g_vbl[4*8*128*TBB];
__device__ __align__(128) char g_wkh[8*32*TBB], g_wkl[8*32*TBB];
__device__ __align__(128) char g_woh[8*32*TBB], g_wol[8*32*TBB];
__device__ __align__(128) char g_wqh[8*32*TA],  g_wql[8*32*TA];
__device__ __align__(128) char g_wvh[8*32*TA],  g_wvl[8*32*TA];
__device__ __align__(128) char g_pkth[4*8*128*TA], g_pktl[4*8*128*TA];
__device__ __align__(128) char g_wvwoh[8*32*TBB], g_wvwol[8*32*TBB];
__device__ __align__(128) char g_kvrh[4*8*32*TA], g_kvrl[4*8*32*TA];
__device__ __align__(128) char g_kvoh[4*8*32*TBB], g_kvol[4*8*32*TBB];
__device__ __align__(128) char g_finh[4*8*32*TBB], g_finl[4*8*32*TBB];
__device__ unsigned int g_barA[2];
__device__ unsigned int g_barD[2];

// ---------------- PTX helpers ----------------
__device__ __forceinline__ uint32_t s2u(const void* p) {
    uint32_t a;
    asm("{ .reg .u64 t; cvta.to.shared.u64 t, %1; cvt.u32.u64 %0, t; }" : "=r"(a) : "l"(p));
    return a;
}
#define MBARRIER_INIT(addr, cnt) \
    asm volatile("mbarrier.init.shared.b64 [%0], %1;" :: "r"((uint32_t)(addr)), "r"((uint32_t)(cnt)) : "memory")
#define MBARRIER_EXPECT_TX(addr, bytes) \
    asm volatile("mbarrier.arrive.expect_tx.shared.b64 _, [%0], %1;" :: "r"((uint32_t)(addr)), "r"((uint32_t)(bytes)) : "memory")
#define MBARRIER_WAIT_PARITY(mbar, par) do { \
    uint32_t _m = (uint32_t)(mbar); uint32_t _p = (uint32_t)(par); uint32_t _d; \
    asm volatile("{\n\t.reg .pred p;\n\tmbarrier.try_wait.parity.acquire.cta.shared::cta.b64 p, [%1], %2;\n\tselp.b32 %0, 1, 0, p;\n\t}" \
        : "=r"(_d) : "r"(_m), "r"(_p) : "memory"); \
    if (!_d) { \
        asm volatile("{\n\t.reg .pred P1;\n\tWL_%=:\n\tmbarrier.try_wait.parity.acquire.cta.shared::cta.b64 P1, [%0], %1, 0x989680;\n\t@P1 bra.uni WD_%=;\n\tbra.uni WL_%=;\n\tWD_%=:\n\t}" \
            :: "r"(_m), "r"(_p) : "memory"); \
    } \
} while(0)

__device__ __forceinline__ void bulk_g2s(uint32_t dst, const void* src, uint32_t bytes, uint32_t mbar) {
    asm volatile("cp.async.bulk.shared::cluster.global.mbarrier::complete_tx::bytes [%0], [%1], %2, [%3];"
        :: "r"(dst), "l"(src), "r"(bytes), "r"(mbar) : "memory");
}
__device__ __forceinline__ void ldsm4(uint32_t* r, uint32_t a) {
    asm volatile("ldmatrix.sync.aligned.m8n8.x4.shared.b16 {%0,%1,%2,%3}, [%4];"
        : "=r"(r[0]), "=r"(r[1]), "=r"(r[2]), "=r"(r[3]) : "r"(a));
}
__device__ __forceinline__ void ldsm4t(uint32_t* r, uint32_t a) {
    asm volatile("ldmatrix.sync.aligned.m8n8.x4.trans.shared.b16 {%0,%1,%2,%3}, [%4];"
        : "=r"(r[0]), "=r"(r[1]), "=r"(r[2]), "=r"(r[3]) : "r"(a));
}
__device__ __forceinline__ void mma16816(float* c, const uint32_t* a, const uint32_t* b) {
    asm volatile("mma.sync.aligned.m16n8k16.row.col.f32.f16.f16.f32 "
        "{%0,%1,%2,%3}, {%4,%5,%6,%7}, {%8,%9}, {%0,%1,%2,%3};"
        : "+f"(c[0]), "+f"(c[1]), "+f"(c[2]), "+f"(c[3])
        : "r"(a[0]), "r"(a[1]), "r"(a[2]), "r"(a[3]), "r"(b[0]), "r"(b[1]));
}

__device__ __forceinline__ unsigned short hraw(__half h) { unsigned short u; memcpy(&u, &h, 2); return u; }
__device__ __forceinline__ void split2(float x, float y, uint32_t& H, uint32_t& L) {
    __half hx = __float2half_rn(x), hy = __float2half_rn(y);
    __half lx = __float2half_rn(x - __half2float(hx));
    __half ly = __float2half_rn(y - __half2float(hy));
    H = (uint32_t)hraw(hx) | ((uint32_t)hraw(hy) << 16);
    L = (uint32_t)hraw(lx) | ((uint32_t)hraw(ly) << 16);
}

__device__ __forceinline__ uint32_t a_off(int row, int kbyte) {
    int p = row >> 1;
    int c = (row & 1) * 4 + (kbyte >> 4);
    return (uint32_t)p * 128 + (uint32_t)((c ^ (p & 7)) * 16) + (kbyte & 15);
}
__device__ __forceinline__ uint32_t b_off(int r, int nbyte) {
    int q = nbyte >> 7;
    int c = (nbyte & 127) >> 4;
    return (uint32_t)q * 4096 + (uint32_t)r * 128 + (uint32_t)((c ^ (r & 7)) * 16) + (nbyte & 15);
}

// grid-wide barrier (n = total participating blocks)
__device__ __forceinline__ void grid_bar(int idx, unsigned int n) {
    __syncthreads();
    if (threadIdx.x == 0) {
        __threadfence();
        atomicAdd(&g_barA[idx], 1u);
        while (*((volatile unsigned int*)&g_barA[idx]) < n) __nanosleep(64);
        __threadfence();
        unsigned int d = atomicAdd(&g_barD[idx], 1u);
        if (d == n - 1) {
            *((volatile unsigned int*)&g_barA[idx]) = 0;
            __threadfence();
            *((volatile unsigned int*)&g_barD[idx]) = 0;
        }
    }
    __syncthreads();
}

// ---------------- conversion bodies ----------------
__device__ __forceinline__ void conv_unitA(const float* __restrict__ src, char* hi, char* lo, int idx) {
    int m = idx >> 7;
    int u0 = (idx & 127) << 3;
    const float4* s = reinterpret_cast<const float4*>(src + ((size_t)m << 10) + u0);
    float4 a = s[0], b = s[1];
    uint32_t h[4], l[4];
    split2(a.x, a.y, h[0], l[0]); split2(a.z, a.w, h[1], l[1]);
    split2(b.x, b.y, h[2], l[2]); split2(b.z, b.w, h[3], l[3]);
    size_t tile = ((size_t)(m >> 7) * 32 + (u0 >> 5)) * TA;
    uint32_t off = a_off(m & 127, (u0 & 31) * 2);
    *reinterpret_cast<uint4*>(hi + tile + off) = make_uint4(h[0], h[1], h[2], h[3]);
    *reinterpret_cast<uint4*>(lo + tile + off) = make_uint4(l[0], l[1], l[2], l[3]);
}
__device__ __forceinline__ void conv_unitV(const float* __restrict__ v, int idx) {
    int m = idx >> 7;
    int u0 = (idx & 127) << 3;
    const float4* s = reinterpret_cast<const float4*>(v + ((size_t)m << 10) + u0);
    float4 a = s[0], b = s[1];
    uint32_t h[4], l[4];
    split2(a.x, a.y, h[0], l[0]); split2(a.z, a.w, h[1], l[1]);
    split2(b.x, b.y, h[2], l[2]); split2(b.z, b.w, h[3], l[3]);
    int batch = m >> 12, sloc = m & 4095;
    size_t tile = ((size_t)(batch * 8 + (u0 >> 7)) * 128 + (sloc >> 5)) * TBB;
    uint32_t off = b_off(sloc & 31, (u0 & 127) * 2);
    *reinterpret_cast<uint4*>(g_vbh + tile + off) = make_uint4(h[0], h[1], h[2], h[3]);
    *reinterpret_cast<uint4*>(g_vbl + tile + off) = make_uint4(l[0], l[1], l[2], l[3]);
}

// Launch 1: k conv (blocks 0..8191) + 4 W convs (blocks 8192..10239)
__global__ void conv_kw(const float* __restrict__ key, const float* __restrict__ Wk,
                        const float* __restrict__ Wo, const float* __restrict__ Wq,
                        const float* __restrict__ Wv) {
    int bid = blockIdx.x;
    if (bid < 8192) {
        conv_unitA(key, g_kh, g_kl, bid * 256 + threadIdx.x);
        return;
    }
    int wb = bid - 8192;
    int zz = wb >> 9;
    int xb = wb & 511;
    const float* W = zz == 0 ? Wk : zz == 1 ? Wo : zz == 2 ? Wq : Wv;
    int idx = xb * 256 + threadIdx.x;
    int r = idx >> 7;
    int c0 = (idx & 127) << 3;
    const float4* s = reinterpret_cast<const float4*>(W + ((size_t)r << 10) + c0);
    float4 a = s[0], b = s[1];
    uint32_t h[4], l[4];
    split2(a.x, a.y, h[0], l[0]); split2(a.z, a.w, h[1], l[1]);
    split2(b.x, b.y, h[2], l[2]); split2(b.z, b.w, h[3], l[3]);
    if (zz < 2) {
        char* hi = zz == 0 ? g_wkh : g_woh;
        char* lo = zz == 0 ? g_wkl : g_wol;
        size_t tile = ((size_t)(c0 >> 7) * 32 + (r >> 5)) * TBB;
        uint32_t off = b_off(r & 31, (c0 & 127) * 2);
        *reinterpret_cast<uint4*>(hi + tile + off) = make_uint4(h[0], h[1], h[2], h[3]);
        *reinterpret_cast<uint4*>(lo + tile + off) = make_uint4(l[0], l[1], l[2], l[3]);
    } else {
        char* hi = zz == 2 ? g_wqh : g_wvh;
        char* lo = zz == 2 ? g_wql : g_wvl;
        size_t tile = ((size_t)(r >> 7) * 32 + (c0 >> 5)) * TA;
        uint32_t off = a_off(r & 127, (c0 & 31) * 2);
        *reinterpret_cast<uint4*>(hi + tile + off) = make_uint4(h[0], h[1], h[2], h[3]);
        *reinterpret_cast<uint4*>(lo + tile + off) = make_uint4(l[0], l[1], l[2], l[3]);
    }
}

// ---------------- shared GEMM mainloop ----------------
// TERMS=3: Ah*Bh + Al*Bh + Ah*Bl.  TERMS=2: Ah*Bh + Ah*Bl (Al not loaded).
template <int TERMS>
__device__ __forceinline__ void refill(uint32_t st0, uint32_t sb, int s,
        const char* Abh, const char* Abl, const char* Bbh, const char* Bbl, int c) {
    MBARRIER_EXPECT_TX(sb + 8 * s, TERMS == 3 ? STG : (STG - TA));
    uint32_t d = st0 + s * STG;
    bulk_g2s(d,            Abh + (size_t)c * TA,  TA,  sb + 8 * s);
    if (TERMS == 3)
        bulk_g2s(d + TA,   Abl + (size_t)c * TA,  TA,  sb + 8 * s);
    bulk_g2s(d + 2 * TA,   Bbh + (size_t)c * TBB, TBB, sb + 8 * s);
    bulk_g2s(d + 2*TA+TBB, Bbl + (size_t)c * TBB, TBB, sb + 8 * s);
}

template <int TERMS>
__device__ __forceinline__ void gemm_core(
        const char* __restrict__ Abh, const char* __restrict__ Abl,
        const char* __restrict__ Bbh, const char* __restrict__ Bbl,
        int kch, uint32_t sb, uint32_t st0, float acc[4][4][4]) {
    const int tid = threadIdx.x, lane = tid & 31, wid = tid >> 5;
    const int wm = wid >> 2, wn = wid & 3;
    const int i = lane & 15, h = lane >> 4;

    if (tid == 0)
        for (int s = 0; s < STAGES; ++s) MBARRIER_INIT(sb + 8 * s, 1);
    __syncthreads();

    if (tid == 0) {
        int np = STAGES < kch ? STAGES : kch;
        for (int s = 0; s < np; ++s) refill<TERMS>(st0, sb, s, Abh, Abl, Bbh, Bbl, s);
    }

#pragma unroll
    for (int ii = 0; ii < 4; ii++)
#pragma unroll
        for (int j = 0; j < 4; j++)
#pragma unroll
            for (int r = 0; r < 4; r++) acc[ii][j][r] = 0.0f;

    const uint32_t aBase = (uint32_t)wm * 4096 + (uint32_t)(i >> 1) * 128;
    const int xA = (i >> 1) & 7;
    const int cA0 = (i & 1) * 4 + h;
    const uint32_t qOff = (uint32_t)(wn >> 1) * 4096;
    const int xB = lane & 7;
    const uint32_t pj0 = (uint32_t)((((wn & 1) * 4 + h)     ^ xB) * 16);
    const uint32_t pj1 = (uint32_t)((((wn & 1) * 4 + h + 2) ^ xB) * 16);
    const uint32_t bRow = (uint32_t)i * 128;

    int s = 0, pf = 0;
    for (int c = 0; c < kch; ++c) {
        MBARRIER_WAIT_PARITY(sb + 8 * s, pf);
        uint32_t sa = st0 + s * STG;
#pragma unroll
        for (int k16 = 0; k16 < 2; ++k16) {
            uint32_t bb = sa + 2 * TA + qOff + bRow + k16 * 2048;
            uint32_t bh[4][2], bl4[4][2], t[4];
            ldsm4t(t, bb + pj0);        bh[0][0]=t[0]; bh[0][1]=t[1]; bh[1][0]=t[2]; bh[1][1]=t[3];
            ldsm4t(t, bb + pj1);        bh[2][0]=t[0]; bh[2][1]=t[1]; bh[3][0]=t[2]; bh[3][1]=t[3];
            ldsm4t(t, bb + TBB + pj0);  bl4[0][0]=t[0]; bl4[0][1]=t[1]; bl4[1][0]=t[2]; bl4[1][1]=t[3];
            ldsm4t(t, bb + TBB + pj1);  bl4[2][0]=t[0]; bl4[2][1]=t[1]; bl4[3][0]=t[2]; bl4[3][1]=t[3];
            uint32_t aoff = (uint32_t)(((cA0 + k16 * 2) ^ xA) * 16);
            uint32_t ab = sa + aBase + aoff;
#pragma unroll
            for (int mf = 0; mf < 4; ++mf) {
                uint32_t ah[4];
                ldsm4(ah, ab + mf * 1024);
                if (TERMS == 3) {
                    uint32_t al4[4];
                    ldsm4(al4, ab + TA + mf * 1024);
#pragma unroll
                    for (int nf = 0; nf < 4; ++nf) {
                        mma16816(acc[mf][nf], ah, bh[nf]);
                        mma16816(acc[mf][nf], al4, bh[nf]);
                        mma16816(acc[mf][nf], ah, bl4[nf]);
                    }
                } else {
#pragma unroll
                    for (int nf = 0; nf < 4; ++nf) {
                        mma16816(acc[mf][nf], ah, bh[nf]);
                        mma16816(acc[mf][nf], ah, bl4[nf]);
                    }
                }
            }
        }
        __syncthreads();
        if (tid == 0 && c + STAGES < kch)
            refill<TERMS>(st0, sb, s, Abh, Abl, Bbh, Bbl, c + STAGES);
        if (++s == STAGES) { s = 0; pf ^= 1; }
    }
}

// ---------------- epilogue helpers ----------------
__device__ __forceinline__ void epi_alayout(float acc[4][4][4], char* outH, char* outL,
                                            size_t mtile_base) {
    const int lane = threadIdx.x & 31, wid = threadIdx.x >> 5;
    const int wm = wid >> 2, wn = wid & 3;
    const int g = lane >> 2, tg = lane & 3;
    size_t mtile = (mtile_base + wn) * TA;
#pragma unroll
    for (int mf = 0; mf < 4; ++mf)
#pragma unroll
        for (int nf = 0; nf < 4; ++nf)
#pragma unroll
            for (int rh = 0; rh < 2; ++rh) {
                int row = wm * 64 + mf * 16 + g + rh * 8;
                uint32_t hw, lw;
                split2(acc[mf][nf][rh * 2], acc[mf][nf][rh * 2 + 1], hw, lw);
                uint32_t off = a_off(row, nf * 16 + tg * 4);
                *reinterpret_cast<uint32_t*>(outH + mtile + off) = hw;
                *reinterpret_cast<uint32_t*>(outL + mtile + off) = lw;
            }
}
__device__ __forceinline__ void epi_blayout(float acc[4][4][4], char* outH, char* outL,
                                            size_t nkbase, int m0) {
    const int lane = threadIdx.x & 31, wid = threadIdx.x >> 5;
    const int wm = wid >> 2, wn = wid & 3;
    const int g = lane >> 2, tg = lane & 3;
#pragma unroll
    for (int mf = 0; mf < 4; ++mf)
#pragma unroll
        for (int rh = 0; rh < 2; ++rh) {
            int row = wm * 64 + mf * 16 + g + rh * 8;
            int kloc = m0 + row;
            size_t tile = (nkbase + (kloc >> 5)) * TBB;
#pragma unroll
            for (int nf = 0; nf < 4; ++nf) {
                uint32_t hw, lw;
                split2(acc[mf][nf][rh * 2], acc[mf][nf][rh * 2 + 1], hw, lw);
                uint32_t off = b_off(kloc & 31, (wn * 32 + nf * 8 + tg * 2) * 2);
                *reinterpret_cast<uint32_t*>(outH + tile + off) = hw;
                *reinterpret_cast<uint32_t*>(outL + tile + off) = lw;
            }
        }
}

// ---------------- GEMM kernels ----------------
// blocks 0..1023: pk3T tiles (2-term); 1024..1087: WvWo (2-term); 1088..1599: conv(q); 1600..2111: conv(v)
__global__ void __launch_bounds__(256, 2)
projkB_gemm(const float* __restrict__ mask, const float* __restrict__ query,
            const float* __restrict__ value) {
    extern __shared__ __align__(1024) char smem[];
    uint32_t sb = s2u(smem), st0 = sb + 1024;
    const int tid = threadIdx.x, lane = tid & 31, wid = tid >> 5;
    const int wm = wid >> 2, wn = wid & 3;
    const int g = lane >> 2, tg = lane & 3;
    const int bid = blockIdx.x;

    if (bid >= 1088) {
        int cb = bid - 1088;
        if (cb < 512) {
#pragma unroll 1
            for (int it = 0; it < 16; ++it)
                conv_unitA(query, g_qh, g_ql, (cb * 16 + it) * 256 + tid);
        } else {
            cb -= 512;
#pragma unroll 1
            for (int it = 0; it < 16; ++it)
                conv_unitV(value, (cb * 16 + it) * 256 + tid);
        }
        return;
    }
    if (bid >= 1024) {
        int b2 = bid - 1024;
        int by = b2 >> 3, bx = b2 & 7;
        float acc[4][4][4];
        gemm_core<2>(g_wvh + (size_t)by * 32 * TA, g_wvl + (size_t)by * 32 * TA,
                     g_woh + (size_t)bx * 32 * TBB, g_wol + (size_t)bx * 32 * TBB,
                     32, sb, st0, acc);
        epi_blayout(acc, g_wvwoh, g_wvwol, (size_t)bx * 32, by * 128);
        return;
    }

    const int by = bid >> 3, bx = bid & 7;
    const int m0 = by * 128;

    float acc[4][4][4];
    gemm_core<2>(g_kh + (size_t)by * 32 * TA, g_kl + (size_t)by * 32 * TA,
                 g_wkh + (size_t)bx * 32 * TBB, g_wkl + (size_t)bx * 32 * TBB,
                 32, sb, st0, acc);
    __syncthreads();

    uint32_t shh = st0, sll = st0 + 34816;
#pragma unroll
    for (int mf = 0; mf < 4; ++mf)
#pragma unroll
        for (int rh = 0; rh < 2; ++rh) {
            int row = wm * 64 + mf * 16 + g + rh * 8;
            float mv = mask[m0 + row];
#pragma unroll
            for (int nf = 0; nf < 4; ++nf) {
                float v0 = acc[mf][nf][rh * 2] * mv;
                float v1 = acc[mf][nf][rh * 2 + 1] * mv;
                v0 = v0 / (1.0f + __expf(-v0)) * mv;
                v1 = v1 / (1.0f + __expf(-v1)) * mv;
                uint32_t hw, lw;
                split2(v0, v1, hw, lw);
                uint32_t a = (uint32_t)row * 272 + (wn * 32 + nf * 8 + tg * 2) * 2;
                asm volatile("st.shared.b32 [%0], %1;" :: "r"(shh + a), "r"(hw) : "memory");
                asm volatile("st.shared.b32 [%0], %1;" :: "r"(sll + a), "r"(lw) : "memory");
            }
        }
    __syncthreads();
    int u = tid & 127;
    int sh2 = (tid >> 7) * 64;
    int bt = by >> 5;
    int kc0 = (m0 & 4095) >> 5;
#pragma unroll
    for (int c8 = 0; c8 < 8; ++c8) {
        int s0 = sh2 + c8 * 8;
        uint32_t hw[4], lw[4];
#pragma unroll
        for (int p = 0; p < 4; ++p) {
            unsigned short h0, h1, l0, l1;
            uint32_t a0 = (uint32_t)(s0 + 2 * p) * 272 + (uint32_t)u * 2;
            uint32_t a1 = a0 + 272;
            asm volatile("ld.shared.b16 %0, [%1];" : "=h"(h0) : "r"(shh + a0));
            asm volatile("ld.shared.b16 %0, [%1];" : "=h"(h1) : "r"(shh + a1));
            asm volatile("ld.shared.b16 %0, [%1];" : "=h"(l0) : "r"(sll + a0));
            asm volatile("ld.shared.b16 %0, [%1];" : "=h"(l1) : "r"(sll + a1));
            hw[p] = (uint32_t)h0 | ((uint32_t)h1 << 16);
            lw[p] = (uint32_t)l0 | ((uint32_t)l1 << 16);
        }
        size_t tile = ((size_t)(bt * 8 + bx) * 128 + kc0 + (s0 >> 5)) * TA;
        uint32_t off = a_off(u, (s0 & 31) * 2);
        *reinterpret_cast<uint4*>(g_pkth + tile + off) = make_uint4(hw[0], hw[1], hw[2], hw[3]);
        *reinterpret_cast<uint4*>(g_pktl + tile + off) = make_uint4(lw[0], lw[1], lw[2], lw[3]);
    }
}

// Fused kvr -> kvo -> wqkvo, 256 blocks all resident. All phases 2-term fp16.
__global__ void __launch_bounds__(256, 2)
kvx_gemm() {
    extern __shared__ __align__(1024) char smem[];
    uint32_t sb = s2u(smem), st0 = sb + 1024;
    const int bid = blockIdx.x;
    const int b = bid >> 6, by = (bid >> 3) & 7, bx = bid & 7;

    float acc[4][4][4];
    gemm_core<2>(g_pkth + (size_t)(b * 8 + by) * 128 * TA, g_pktl + (size_t)(b * 8 + by) * 128 * TA,
                 g_vbh + (size_t)(b * 8 + bx) * 128 * TBB, g_vbl + (size_t)(b * 8 + bx) * 128 * TBB,
                 128, sb, st0, acc);
    epi_alayout(acc, g_kvrh, g_kvrl, (size_t)(b * 8 + by) * 32 + bx * 4);

    grid_bar(0, 256);

    gemm_core<2>(g_kvrh + (size_t)(b * 8 + by) * 32 * TA, g_kvrl + (size_t)(b * 8 + by) * 32 * TA,
                 g_wvwoh + (size_t)bx * 32 * TBB, g_wvwol + (size_t)bx * 32 * TBB,
                 32, sb, st0, acc);
    epi_blayout(acc, g_kvoh, g_kvol, (size_t)(b * 8 + bx) * 32, by * 128);

    grid_bar(1, 256);

    gemm_core<2>(g_wqh + (size_t)by * 32 * TA, g_wql + (size_t)by * 32 * TA,
                 g_kvoh + (size_t)(b * 8 + bx) * 32 * TBB, g_kvol + (size_t)(b * 8 + bx) * 32 * TBB,
                 32, sb, st0, acc);
    epi_blayout(acc, g_finh, g_finl, (size_t)(b * 8 + bx) * 32, by * 128);
}

// out[b] = q[b] @ fin[b] -> f32 (2-term)
__global__ void __launch_bounds__(256, 2)
final_gemm(float* __restrict__ outF) {
    extern __shared__ __align__(1024) char smem[];
    uint32_t sb = s2u(smem), st0 = sb + 1024;
    const int tid = threadIdx.x, lane = tid & 31, wid = tid >> 5;
    const int wm = wid >> 2, wn = wid & 3;
    const int bx = blockIdx.x, by = blockIdx.y, z = blockIdx.z;
    const int g = lane >> 2, tg = lane & 3;
    const int mb = z * 32 + by;
    const int n0 = bx * 128;

    float acc[4][4][4];
    gemm_core<2>(g_qh + (size_t)mb * 32 * TA, g_ql + (size_t)mb * 32 * TA,
                 g_finh + (size_t)(z * 8 + bx) * 32 * TBB, g_finl + (size_t)(z * 8 + bx) * 32 * TBB,
                 32, sb, st0, acc);

#pragma unroll
    for (int mf = 0; mf < 4; ++mf)
#pragma unroll
        for (int nf = 0; nf < 4; ++nf)
#pragma unroll
            for (int rh = 0; rh < 2; ++rh) {
                int row = wm * 64 + mf * 16 + g + rh * 8;
                int gcol = n0 + wn * 32 + nf * 8 + tg * 2;
                float2 v = make_float2(acc[mf][nf][rh * 2], acc[mf][nf][rh * 2 + 1]);
                *reinterpret_cast<float2*>(outF + ((size_t)mb * 128 + row) * 1024 + gcol) = v;
            }
}

// ---------------- launch ----------------
extern "C" void kernel_launch(void* const* d_in, const int* in_sizes, int n_in,
                              void* d_out, int out_size) {
    const float* query = (const float*)d_in[0];
    const float* key   = (const float*)d_in[1];
    const float* value = (const float*)d_in[2];
    const float* mask  = (const float*)d_in[3];
    const float* Wk    = (const float*)d_in[4];
    const float* Wv    = (const float*)d_in[5];
    const float* Wq    = (const float*)d_in[6];
    const float* Wo    = (const float*)d_in[7];
    float* out = (float*)d_out;

    static bool attr_done = false;
    if (!attr_done) {
        cudaFuncSetAttribute(projkB_gemm, cudaFuncAttributeMaxDynamicSharedMemorySize, SMEM_SZ);
        cudaFuncSetAttribute(kvx_gemm,    cudaFuncAttributeMaxDynamicSharedMemorySize, SMEM_SZ);
        cudaFuncSetAttribute(final_gemm,  cudaFuncAttributeMaxDynamicSharedMemorySize, SMEM_SZ);
        attr_done = true;
    }

    conv_kw<<<10240, 256>>>(key, Wk, Wo, Wq, Wv);
    projkB_gemm<<<2112, 256, SMEM_SZ>>>(mask, query, value);
    kvx_gemm<<<256, 256, SMEM_SZ>>>();
    final_gemm<<<dim3(8, 32, 4), 256, SMEM_SZ>>>(out);
}